// round 7
// baseline (speedup 1.0000x reference)
#include <cuda_runtime.h>
#include <math.h>
#include <stdint.h>

#define IN_DIM 1024
#define ED 256
#define NE 512
#define NTOK_MAX 131072
#define TT 32
#define PS_PITCH 260
#define XDP 132
#define BK1 32
#define BK2 16

typedef unsigned long long u64;
typedef uint32_t u32;

__device__ __align__(16) float g_WT[2 * IN_DIM * 128];   // [nblk][k][128]
__device__ __align__(16) float g_cnT[ED * NE];           // normalized centers [k][e]
__device__ __align__(16) float g_P[(size_t)NTOK_MAX * ED];
__device__ float g_sqp[2 * NTOK_MAX];                    // per-nblk sumsq partials

static __device__ __forceinline__ u64 pack2(float lo, float hi) {
    u64 r; asm("mov.b64 %0, {%1, %2};" : "=l"(r) : "f"(lo), "f"(hi)); return r;
}
static __device__ __forceinline__ void unpack2(u64 v, float& lo, float& hi) {
    asm("mov.b64 {%0, %1}, %2;" : "=f"(lo), "=f"(hi) : "l"(v));
}
static __device__ __forceinline__ void ffma2(u64& d, u64 a, u64 b) {
    asm("fma.rn.f32x2 %0, %1, %2, %0;" : "+l"(d) : "l"(a), "l"(b));
}
static __device__ __forceinline__ void fadd2(u64& d, u64 a) {
    asm("add.rn.f32x2 %0, %0, %1;" : "+l"(d) : "l"(a));
}

// ---- bulk async copy + mbarrier helpers ----
static __device__ __forceinline__ void mbar_init(u32 mbar, u32 cnt) {
    asm volatile("mbarrier.init.shared.b64 [%0], %1;" :: "r"(mbar), "r"(cnt) : "memory");
}
static __device__ __forceinline__ void mbar_expect_tx(u32 mbar, u32 bytes) {
    asm volatile("mbarrier.arrive.expect_tx.shared.b64 _, [%0], %1;" :: "r"(mbar), "r"(bytes) : "memory");
}
static __device__ __forceinline__ void bulk_g2s(u32 dst, const float* src,
                                                u32 bytes, u32 mbar) {
    asm volatile("cp.async.bulk.shared::cta.global.mbarrier::complete_tx::bytes [%0], [%1], %2, [%3];"
                 :: "r"(dst), "l"(src), "r"(bytes), "r"(mbar) : "memory");
}
static __device__ __forceinline__ void mbar_wait(u32 mbar, u32 parity) {
    u32 done;
    asm volatile(
        "{\n\t.reg .pred p;\n\t"
        "mbarrier.try_wait.parity.acquire.cta.shared::cta.b64 p, [%1], %2;\n\t"
        "selp.b32 %0, 1, 0, p;\n\t}"
        : "=r"(done) : "r"(mbar), "r"(parity) : "memory");
    if (!done) {
        asm volatile(
            "{\n\t.reg .pred P1;\n\t"
            "WL_%=:\n\t"
            "mbarrier.try_wait.parity.acquire.cta.shared::cta.b64 P1, [%0], %1, 0x989680;\n\t"
            "@P1 bra.uni WD_%=;\n\t"
            "bra.uni WL_%=;\n\t"
            "WD_%=:\n\t}"
            :: "r"(mbar), "r"(parity) : "memory");
    }
}

static __device__ __forceinline__ void upd(float v, int i,
                                           float& v1, int& i1, float& v2, int& i2) {
    if (v > v1 || (v == v1 && i < i1)) { v2 = v1; i2 = i1; v1 = v; i1 = i; }
    else if (v > v2 || (v == v2 && i < i2)) { v2 = v; i2 = i; }
}

// ---------------- prep: normalize centers -> g_cnT [k][e] ----------------
__global__ void cnorm_kernel(const float* __restrict__ centers) {
    __shared__ float ws[8];
    int e = blockIdx.x, t = threadIdx.x;
    float v = centers[e * ED + t];
    float s = v * v;
    #pragma unroll
    for (int o = 16; o; o >>= 1) s += __shfl_xor_sync(0xffffffffu, s, o);
    if ((t & 31) == 0) ws[t >> 5] = s;
    __syncthreads();
    float tot = 0.f;
    #pragma unroll
    for (int i = 0; i < 8; ++i) tot += ws[i];
    float norm = fmaxf(sqrtf(tot), 1e-12f);
    g_cnT[t * NE + e] = v / norm;
}

// ---------------- prep: transpose W [n][k] -> g_WT [nblk][k][128] ----------------
__global__ void prep_wt_kernel(const float* __restrict__ W) {
    __shared__ float t[32][33];
    int bx = blockIdx.x * 32;   // k block
    int by = blockIdx.y * 32;   // n block
    int x = threadIdx.x, y = threadIdx.y;
    #pragma unroll
    for (int j = 0; j < 32; j += 8)
        t[y + j][x] = W[(size_t)(by + y + j) * IN_DIM + bx + x];
    __syncthreads();
    const int nblk = by >> 7;
    const int nloc0 = by & 127;
    #pragma unroll
    for (int j = 0; j < 32; j += 8)
        g_WT[(size_t)nblk * (IN_DIM * 128) + (size_t)(bx + y + j) * 128 + nloc0 + x] = t[x][y + j];
}

// ---------------- K1: P = x @ W^T + b  (64m x 128n, 3 CTAs/SM) ----------------
#define W1BYTES (BK1 * 128 * 4)

__global__ __launch_bounds__(256, 3)
void k1_kernel(const float* __restrict__ x, const float* __restrict__ bias) {
    extern __shared__ __align__(16) float sm1[];
    float* xd = sm1;                       // [2][BK1][XDP]  duplicated x, k-major
    float* wS = sm1 + 2 * BK1 * XDP;       // [2][BK1][128]  W tile, k-major
    __shared__ __align__(8) u64 mbars[2];

    const int tid = threadIdx.x;
    const int w = tid >> 5, lane = tid & 31;
    const int t0 = blockIdx.x * 64;
    const int nblk = blockIdx.y;
    const int mb = w * 8;
    const int nA = lane * 4;               // 0..124 within this 128-block

    const int xr = tid >> 2, xk = (tid & 3) * 8;
    const float* xp = x + (size_t)(t0 + xr) * IN_DIM + xk;
    const float* wsrc = g_WT + (size_t)nblk * (IN_DIM * 128);

    u32 wS_u32 = (u32)__cvta_generic_to_shared(wS);
    u32 mb0 = (u32)__cvta_generic_to_shared(&mbars[0]);
    u32 mb1 = mb0 + 8;
    int ph0 = 0, ph1 = 0;

    u64 acc[8][2];
    #pragma unroll
    for (int m = 0; m < 8; ++m) { acc[m][0] = 0ull; acc[m][1] = 0ull; }

    if (tid == 0) { mbar_init(mb0, 1); mbar_init(mb1, 1); }
    __syncthreads();

    if (tid == 0) { mbar_expect_tx(mb0, W1BYTES); bulk_g2s(wS_u32, wsrc, W1BYTES, mb0); }
    float4 xs0 = *(const float4*)xp;
    float4 xs1 = *(const float4*)(xp + 4);
    {
        float v[8] = {xs0.x, xs0.y, xs0.z, xs0.w, xs1.x, xs1.y, xs1.z, xs1.w};
        #pragma unroll
        for (int i = 0; i < 8; ++i)
            *(float2*)(xd + (xk + i) * XDP + 2 * xr) = make_float2(v[i], v[i]);
    }
    mbar_wait(mb0, ph0); ph0 ^= 1;
    __syncthreads();

    const int NT = IN_DIM / BK1;
    for (int kt = 0; kt < NT; ++kt) {
        const int buf = kt & 1;
        const float* xb = xd + buf * (BK1 * XDP);
        const float* wb = wS + buf * (BK1 * 128);
        if (kt + 1 < NT) {
            if (tid == 0) {
                u32 m = buf ? mb0 : mb1;
                mbar_expect_tx(m, W1BYTES);
                bulk_g2s(wS_u32 + (u32)((buf ^ 1) * W1BYTES),
                         wsrc + (size_t)(kt + 1) * BK1 * 128, W1BYTES, m);
            }
            xs0 = *(const float4*)(xp + (kt + 1) * BK1);
            xs1 = *(const float4*)(xp + (kt + 1) * BK1 + 4);
        }
        #pragma unroll
        for (int k = 0; k < BK1; ++k) {
            ulonglong2 qa0 = *(const ulonglong2*)(xb + k * XDP + 2 * mb + 0);
            ulonglong2 qa1 = *(const ulonglong2*)(xb + k * XDP + 2 * mb + 4);
            ulonglong2 qa2 = *(const ulonglong2*)(xb + k * XDP + 2 * mb + 8);
            ulonglong2 qa3 = *(const ulonglong2*)(xb + k * XDP + 2 * mb + 12);
            ulonglong2 qb = *(const ulonglong2*)(wb + k * 128 + nA);
            u64 B0 = qb.x, B1 = qb.y;
            ffma2(acc[0][0], qa0.x, B0); ffma2(acc[0][1], qa0.x, B1);
            ffma2(acc[1][0], qa0.y, B0); ffma2(acc[1][1], qa0.y, B1);
            ffma2(acc[2][0], qa1.x, B0); ffma2(acc[2][1], qa1.x, B1);
            ffma2(acc[3][0], qa1.y, B0); ffma2(acc[3][1], qa1.y, B1);
            ffma2(acc[4][0], qa2.x, B0); ffma2(acc[4][1], qa2.x, B1);
            ffma2(acc[5][0], qa2.y, B0); ffma2(acc[5][1], qa2.y, B1);
            ffma2(acc[6][0], qa3.x, B0); ffma2(acc[6][1], qa3.x, B1);
            ffma2(acc[7][0], qa3.y, B0); ffma2(acc[7][1], qa3.y, B1);
        }
        if (kt + 1 < NT) {
            float* xn = xd + (buf ^ 1) * (BK1 * XDP);
            float v[8] = {xs0.x, xs0.y, xs0.z, xs0.w, xs1.x, xs1.y, xs1.z, xs1.w};
            #pragma unroll
            for (int i = 0; i < 8; ++i)
                *(float2*)(xn + (xk + i) * XDP + 2 * xr) = make_float2(v[i], v[i]);
            if (buf) { mbar_wait(mb0, ph0); ph0 ^= 1; }
            else     { mbar_wait(mb1, ph1); ph1 ^= 1; }
        }
        __syncthreads();
    }

    // epilogue: +bias (packed), partial sumsq butterfly, store P + g_sqp
    u64 bp0 = *(const u64*)(bias + nblk * 128 + nA);
    u64 bp1 = *(const u64*)(bias + nblk * 128 + nA + 2);
    #pragma unroll
    for (int m = 0; m < 8; ++m) {
        fadd2(acc[m][0], bp0); fadd2(acc[m][1], bp1);
        u64 sp = 0ull;
        ffma2(sp, acc[m][0], acc[m][0]); ffma2(sp, acc[m][1], acc[m][1]);
        float lo, hi; unpack2(sp, lo, hi);
        float s = lo + hi;
        #pragma unroll
        for (int o = 16; o; o >>= 1) s += __shfl_xor_sync(0xffffffffu, s, o);
        int row = t0 + mb + m;
        ulonglong2 st; st.x = acc[m][0]; st.y = acc[m][1];
        *(ulonglong2*)(g_P + (size_t)row * ED + nblk * 128 + nA) = st;
        if (lane == 0) g_sqp[nblk * NTOK_MAX + row] = s;
    }
}

// ---------------- K2: sims + top-2 + softmax (round-4 proven form) ----------------
#define C2BYTES (BK2 * NE * 4)

__global__ __launch_bounds__(256, 2)
void k2_kernel(float* __restrict__ out, int ntok) {
    extern __shared__ __align__(16) float sm2[];
    float* Ps = sm2;                       // [TT][PS_PITCH] P rows
    float* ct = sm2 + TT * PS_PITCH;       // [2][BK2][NE] center tiles
    __shared__ __align__(8) u64 mbars[2];

    const int tid = threadIdx.x;
    const int w = tid >> 5, lane = tid & 31;
    const int t0 = blockIdx.x * TT;
    const int mb = (w >> 1) * 8;           // 8 tokens per warp-pair
    const int nh = (w & 1) * 256;          // expert half
    const int nA = nh + lane * 4, nB = nh + 128 + lane * 4;

    u32 ct_u32 = (u32)__cvta_generic_to_shared(ct);
    u32 mb0 = (u32)__cvta_generic_to_shared(&mbars[0]);
    u32 mb1 = mb0 + 8;
    int ph0 = 0, ph1 = 0;

    if (tid == 0) { mbar_init(mb0, 1); mbar_init(mb1, 1); }
    __syncthreads();
    if (tid == 0) { mbar_expect_tx(mb0, C2BYTES); bulk_g2s(ct_u32, g_cnT, C2BYTES, mb0); }

    // load P tile (coalesced, overlaps bulk copy)
    const int pr = tid >> 3, pcq = (tid & 7) * 4;
    #pragma unroll
    for (int j = 0; j < 8; ++j) {
        int c = pcq + 32 * j;
        float4 v = *(const float4*)(g_P + (size_t)(t0 + pr) * ED + c);
        *(float4*)(Ps + pr * PS_PITCH + c) = v;
    }
    mbar_wait(mb0, ph0); ph0 ^= 1;
    __syncthreads();

    u64 acc[4][8];
    #pragma unroll
    for (int p = 0; p < 4; ++p)
        #pragma unroll
        for (int j = 0; j < 8; ++j) acc[p][j] = 0ull;

    const int NT = ED / BK2;
    for (int kt = 0; kt < NT; ++kt) {
        const int buf = kt & 1;
        const float* cb = ct + buf * (BK2 * NE);
        if (kt + 1 < NT && tid == 0) {
            u32 m = buf ? mb0 : mb1;
            mbar_expect_tx(m, C2BYTES);
            bulk_g2s(ct_u32 + (u32)((buf ^ 1) * C2BYTES),
                     g_cnT + (size_t)(kt + 1) * BK2 * NE, C2BYTES, m);
        }
        #pragma unroll
        for (int k = 0; k < BK2; ++k) {
            const int kk = kt * BK2 + k;
            u64 a[4];
            #pragma unroll
            for (int p = 0; p < 4; ++p) {
                float l = Ps[(mb + 2 * p) * PS_PITCH + kk];
                float h = Ps[(mb + 2 * p + 1) * PS_PITCH + kk];
                a[p] = pack2(l, h);
            }
            float4 b0 = *(const float4*)(cb + k * NE + nA);
            float4 b1 = *(const float4*)(cb + k * NE + nB);
            u64 bb0 = pack2(b0.x, b0.x), bb1 = pack2(b0.y, b0.y);
            u64 bb2 = pack2(b0.z, b0.z), bb3 = pack2(b0.w, b0.w);
            u64 bb4 = pack2(b1.x, b1.x), bb5 = pack2(b1.y, b1.y);
            u64 bb6 = pack2(b1.z, b1.z), bb7 = pack2(b1.w, b1.w);
            ffma2(acc[0][0], a[0], bb0); ffma2(acc[0][1], a[0], bb1);
            ffma2(acc[0][2], a[0], bb2); ffma2(acc[0][3], a[0], bb3);
            ffma2(acc[0][4], a[0], bb4); ffma2(acc[0][5], a[0], bb5);
            ffma2(acc[0][6], a[0], bb6); ffma2(acc[0][7], a[0], bb7);
            ffma2(acc[1][0], a[1], bb0); ffma2(acc[1][1], a[1], bb1);
            ffma2(acc[1][2], a[1], bb2); ffma2(acc[1][3], a[1], bb3);
            ffma2(acc[1][4], a[1], bb4); ffma2(acc[1][5], a[1], bb5);
            ffma2(acc[1][6], a[1], bb6); ffma2(acc[1][7], a[1], bb7);
            ffma2(acc[2][0], a[2], bb0); ffma2(acc[2][1], a[2], bb1);
            ffma2(acc[2][2], a[2], bb2); ffma2(acc[2][3], a[2], bb3);
            ffma2(acc[2][4], a[2], bb4); ffma2(acc[2][5], a[2], bb5);
            ffma2(acc[2][6], a[2], bb6); ffma2(acc[2][7], a[2], bb7);
            ffma2(acc[3][0], a[3], bb0); ffma2(acc[3][1], a[3], bb1);
            ffma2(acc[3][2], a[3], bb2); ffma2(acc[3][3], a[3], bb3);
            ffma2(acc[3][4], a[3], bb4); ffma2(acc[3][5], a[3], bb5);
            ffma2(acc[3][6], a[3], bb6); ffma2(acc[3][7], a[3], bb7);
        }
        if (kt + 1 < NT) {
            if (buf) { mbar_wait(mb0, ph0); ph0 ^= 1; }
            else     { mbar_wait(mb1, ph1); ph1 ^= 1; }
        }
        __syncthreads();
    }

    // per-thread -> per-warp top-2 over this warp's 256-expert half
    float v1[8], v2[8]; int i1[8], i2[8];
    #pragma unroll
    for (int r = 0; r < 8; ++r) { v1[r] = -INFINITY; v2[r] = -INFINITY; i1[r] = 0; i2[r] = 0; }
    #pragma unroll
    for (int p = 0; p < 4; ++p)
        #pragma unroll
        for (int j = 0; j < 8; ++j) {
            float lo, hi; unpack2(acc[p][j], lo, hi);
            int gi = (j < 4) ? (nA + j) : (nB + j - 4);
            upd(lo, gi, v1[2 * p],     i1[2 * p],     v2[2 * p],     i2[2 * p]);
            upd(hi, gi, v1[2 * p + 1], i1[2 * p + 1], v2[2 * p + 1], i2[2 * p + 1]);
        }
    #pragma unroll
    for (int r = 0; r < 8; ++r)
        #pragma unroll
        for (int o = 16; o; o >>= 1) {
            float o1 = __shfl_xor_sync(0xffffffffu, v1[r], o);
            int  oi1 = __shfl_xor_sync(0xffffffffu, i1[r], o);
            float o2 = __shfl_xor_sync(0xffffffffu, v2[r], o);
            int  oi2 = __shfl_xor_sync(0xffffffffu, i2[r], o);
            upd(o1, oi1, v1[r], i1[r], v2[r], i2[r]);
            upd(o2, oi2, v1[r], i1[r], v2[r], i2[r]);
        }

    // cross-half merge via smem (reuse ct region, safe after last sync)
    float4* mg = (float4*)ct;              // [TT][2]
    if (lane == 0) {
        #pragma unroll
        for (int r = 0; r < 8; ++r)
            mg[(mb + r) * 2 + (w & 1)] =
                make_float4(v1[r], __int_as_float(i1[r]), v2[r], __int_as_float(i2[r]));
    }
    __syncthreads();

    if (tid < TT) {
        float4 A = mg[tid * 2 + 0];
        float4 B = mg[tid * 2 + 1];
        float V1 = A.x, V2 = A.z;
        int I1 = __float_as_int(A.y), I2 = __float_as_int(A.w);
        upd(B.x, __float_as_int(B.y), V1, I1, V2, I2);
        upd(B.z, __float_as_int(B.w), V1, I1, V2, I2);
        int token = t0 + tid;
        float sq = g_sqp[token] + g_sqp[NTOK_MAX + token];
        float inv = 1.f / fmaxf(sqrtf(sq), 1e-12f);
        float e2 = expf((V2 - V1) * inv);
        float den = 1.f + e2;
        out[2 * token]     = 1.f / den;
        out[2 * token + 1] = e2 / den;
        float* oi = out + 2 * (size_t)ntok;
        oi[2 * token]     = (float)I1;
        oi[2 * token + 1] = (float)I2;
    }
}

extern "C" void kernel_launch(void* const* d_in, const int* in_sizes, int n_in,
                              void* d_out, int out_size) {
    const float* x = (const float*)d_in[0];
    const float* W = (const float*)d_in[1];
    const float* b = (const float*)d_in[2];
    const float* c = (const float*)d_in[3];
    int ntok = in_sizes[0] / IN_DIM;   // 131072

    cnorm_kernel<<<NE, ED>>>(c);
    prep_wt_kernel<<<dim3(IN_DIM / 32, ED / 32), dim3(32, 8)>>>(W);

    int smem1 = (2 * BK1 * XDP + 2 * BK1 * 128) * (int)sizeof(float);  // 66560 B
    cudaFuncSetAttribute(k1_kernel, cudaFuncAttributeMaxDynamicSharedMemorySize, smem1);
    k1_kernel<<<dim3(ntok / 64, 2), 256, smem1>>>(x, b);

    int smem2 = (TT * PS_PITCH + 2 * BK2 * NE) * (int)sizeof(float);   // 98816 B
    cudaFuncSetAttribute(k2_kernel, cudaFuncAttributeMaxDynamicSharedMemorySize, smem2);
    k2_kernel<<<ntok / TT, 256, smem2>>>((float*)d_out, ntok);
}

// round 8
// speedup vs baseline: 1.2451x; 1.2451x over previous
#include <cuda_runtime.h>
#include <math.h>
#include <stdint.h>

#define IN_DIM 1024
#define ED 256
#define NE 512
#define NTOK_MAX 131072
#define TT 32
#define PSTP 34
#define XDP 132
#define BK1 32
#define BK2 16

typedef unsigned long long u64;
typedef uint32_t u32;

__device__ __align__(16) float g_WT[IN_DIM * ED];     // W transposed [k][n]
__device__ __align__(16) float g_cnT[ED * NE];        // normalized centers [k][e]
__device__ __align__(16) float g_P[(size_t)NTOK_MAX * ED];
__device__ float g_sq[NTOK_MAX];

static __device__ __forceinline__ u64 pack2(float lo, float hi) {
    u64 r; asm("mov.b64 %0, {%1, %2};" : "=l"(r) : "f"(lo), "f"(hi)); return r;
}
static __device__ __forceinline__ void unpack2(u64 v, float& lo, float& hi) {
    asm("mov.b64 {%0, %1}, %2;" : "=f"(lo), "=f"(hi) : "l"(v));
}
static __device__ __forceinline__ void ffma2(u64& d, u64 a, u64 b) {
    asm("fma.rn.f32x2 %0, %1, %2, %0;" : "+l"(d) : "l"(a), "l"(b));
}
static __device__ __forceinline__ void fadd2(u64& d, u64 a) {
    asm("add.rn.f32x2 %0, %0, %1;" : "+l"(d) : "l"(a));
}

// ---- bulk async copy + mbarrier helpers ----
static __device__ __forceinline__ void mbar_init(u32 mbar, u32 cnt) {
    asm volatile("mbarrier.init.shared.b64 [%0], %1;" :: "r"(mbar), "r"(cnt) : "memory");
}
static __device__ __forceinline__ void mbar_expect_tx(u32 mbar, u32 bytes) {
    asm volatile("mbarrier.arrive.expect_tx.shared.b64 _, [%0], %1;" :: "r"(mbar), "r"(bytes) : "memory");
}
static __device__ __forceinline__ void mbar_arrive(u32 mbar) {
    asm volatile("mbarrier.arrive.shared.b64 _, [%0];" :: "r"(mbar) : "memory");
}
static __device__ __forceinline__ void bulk_g2s(u32 dst, const float* src,
                                                u32 bytes, u32 mbar) {
    asm volatile("cp.async.bulk.shared::cta.global.mbarrier::complete_tx::bytes [%0], [%1], %2, [%3];"
                 :: "r"(dst), "l"(src), "r"(bytes), "r"(mbar) : "memory");
}
static __device__ __forceinline__ void mbar_wait(u32 mbar, u32 parity) {
    u32 done;
    asm volatile(
        "{\n\t.reg .pred p;\n\t"
        "mbarrier.try_wait.parity.acquire.cta.shared::cta.b64 p, [%1], %2;\n\t"
        "selp.b32 %0, 1, 0, p;\n\t}"
        : "=r"(done) : "r"(mbar), "r"(parity) : "memory");
    if (!done) {
        asm volatile(
            "{\n\t.reg .pred P1;\n\t"
            "WL_%=:\n\t"
            "mbarrier.try_wait.parity.acquire.cta.shared::cta.b64 P1, [%0], %1, 0x989680;\n\t"
            "@P1 bra.uni WD_%=;\n\t"
            "bra.uni WL_%=;\n\t"
            "WD_%=:\n\t}"
            :: "r"(mbar), "r"(parity) : "memory");
    }
}

static __device__ __forceinline__ void upd(float v, int i,
                                           float& v1, int& i1, float& v2, int& i2) {
    if (v > v1 || (v == v1 && i < i1)) { v2 = v1; i2 = i1; v1 = v; i1 = i; }
    else if (v > v2 || (v == v2 && i < i2)) { v2 = v; i2 = i; }
}

// ---------------- prep: normalize centers -> g_cnT [k][e] ----------------
__global__ void cnorm_kernel(const float* __restrict__ centers) {
    __shared__ float ws[8];
    int e = blockIdx.x, t = threadIdx.x;
    float v = centers[e * ED + t];
    float s = v * v;
    #pragma unroll
    for (int o = 16; o; o >>= 1) s += __shfl_xor_sync(0xffffffffu, s, o);
    if ((t & 31) == 0) ws[t >> 5] = s;
    __syncthreads();
    float tot = 0.f;
    #pragma unroll
    for (int i = 0; i < 8; ++i) tot += ws[i];
    float norm = fmaxf(sqrtf(tot), 1e-12f);
    g_cnT[t * NE + e] = v / norm;
}

// ---------------- prep: transpose W [n][k] -> g_WT [k][n] ----------------
__global__ void prep_wt_kernel(const float* __restrict__ W) {
    __shared__ float t[32][33];
    int bx = blockIdx.x * 32;
    int by = blockIdx.y * 32;
    int x = threadIdx.x, y = threadIdx.y;
    #pragma unroll
    for (int j = 0; j < 32; j += 8)
        t[y + j][x] = W[(size_t)(by + y + j) * IN_DIM + bx + x];
    __syncthreads();
    #pragma unroll
    for (int j = 0; j < 32; j += 8)
        g_WT[(size_t)(bx + y + j) * ED + by + x] = t[x][y + j];
}

// ---------------- K1: P = x @ W^T + b  (BK=32, producer/consumer pipeline) ----------------
#define W1BYTES (BK1 * ED * 4)

__global__ __launch_bounds__(256, 2)
void k1_kernel(const float* __restrict__ x, const float* __restrict__ bias) {
    extern __shared__ __align__(16) float sm1[];
    float* xd = sm1;                       // [2][BK1][XDP]  duplicated x, k-major (warp-private rows)
    float* wS = sm1 + 2 * BK1 * XDP;       // [2][BK1][ED]   W tile, k-major
    __shared__ __align__(8) u64 mbars[4];  // full0, full1, empty0, empty1

    const int tid = threadIdx.x;
    const int w = tid >> 5, lane = tid & 31;
    const int t0 = blockIdx.x * 64;
    const int mb = w * 8;
    const int nA = lane * 4, nB = 128 + lane * 4;

    const int xr = tid >> 2, xk = (tid & 3) * 8;
    const float* xp = x + (size_t)(t0 + xr) * IN_DIM + xk;

    u32 wS_u32 = (u32)__cvta_generic_to_shared(wS);
    u32 f0 = (u32)__cvta_generic_to_shared(&mbars[0]);
    u32 f1 = f0 + 8, e0 = f0 + 16, e1 = f0 + 24;
    int pf0 = 0, pf1 = 0, pe0 = 0, pe1 = 0;

    u64 acc[8][4];
    #pragma unroll
    for (int m = 0; m < 8; ++m)
        #pragma unroll
        for (int p = 0; p < 4; ++p) acc[m][p] = 0ull;

    if (tid == 0) {
        mbar_init(f0, 1); mbar_init(f1, 1);
        mbar_init(e0, 8); mbar_init(e1, 8);
    }
    __syncthreads();

    // prologue: bulk W tile 0, stage x tile 0 (warp-private)
    if (tid == 0) { mbar_expect_tx(f0, W1BYTES); bulk_g2s(wS_u32, g_WT, W1BYTES, f0); }
    float4 xs0 = *(const float4*)xp;
    float4 xs1 = *(const float4*)(xp + 4);
    {
        float v[8] = {xs0.x, xs0.y, xs0.z, xs0.w, xs1.x, xs1.y, xs1.z, xs1.w};
        #pragma unroll
        for (int i = 0; i < 8; ++i)
            *(float2*)(xd + (xk + i) * XDP + 2 * xr) = make_float2(v[i], v[i]);
    }
    __syncwarp();

    const int NT = IN_DIM / BK1;
    for (int kt = 0; kt < NT; ++kt) {
        const int s = kt & 1;
        if (kt + 1 < NT) {
            if (tid == 0) {
                if (s == 0) {                 // fill buffer 1
                    if (kt) { mbar_wait(e1, pe1); pe1 ^= 1; }
                    mbar_expect_tx(f1, W1BYTES);
                    bulk_g2s(wS_u32 + W1BYTES, g_WT + (size_t)(kt + 1) * BK1 * ED, W1BYTES, f1);
                } else {                      // fill buffer 0 (kt >= 1 always here)
                    mbar_wait(e0, pe0); pe0 ^= 1;
                    mbar_expect_tx(f0, W1BYTES);
                    bulk_g2s(wS_u32, g_WT + (size_t)(kt + 1) * BK1 * ED, W1BYTES, f0);
                }
            }
            xs0 = *(const float4*)(xp + (kt + 1) * BK1);
            xs1 = *(const float4*)(xp + (kt + 1) * BK1 + 4);
        }
        if (s == 0) { mbar_wait(f0, pf0); pf0 ^= 1; }
        else        { mbar_wait(f1, pf1); pf1 ^= 1; }

        const float* xb = xd + s * (BK1 * XDP);
        const float* wb = wS + s * (BK1 * ED);
        #pragma unroll
        for (int k = 0; k < BK1; ++k) {
            ulonglong2 qa0 = *(const ulonglong2*)(xb + k * XDP + 2 * mb + 0);
            ulonglong2 qa1 = *(const ulonglong2*)(xb + k * XDP + 2 * mb + 4);
            ulonglong2 qa2 = *(const ulonglong2*)(xb + k * XDP + 2 * mb + 8);
            ulonglong2 qa3 = *(const ulonglong2*)(xb + k * XDP + 2 * mb + 12);
            ulonglong2 qb0 = *(const ulonglong2*)(wb + k * ED + nA);
            ulonglong2 qb1 = *(const ulonglong2*)(wb + k * ED + nB);
            u64 B0 = qb0.x, B1 = qb0.y, B2 = qb1.x, B3 = qb1.y;
            ffma2(acc[0][0], qa0.x, B0); ffma2(acc[0][1], qa0.x, B1);
            ffma2(acc[0][2], qa0.x, B2); ffma2(acc[0][3], qa0.x, B3);
            ffma2(acc[1][0], qa0.y, B0); ffma2(acc[1][1], qa0.y, B1);
            ffma2(acc[1][2], qa0.y, B2); ffma2(acc[1][3], qa0.y, B3);
            ffma2(acc[2][0], qa1.x, B0); ffma2(acc[2][1], qa1.x, B1);
            ffma2(acc[2][2], qa1.x, B2); ffma2(acc[2][3], qa1.x, B3);
            ffma2(acc[3][0], qa1.y, B0); ffma2(acc[3][1], qa1.y, B1);
            ffma2(acc[3][2], qa1.y, B2); ffma2(acc[3][3], qa1.y, B3);
            ffma2(acc[4][0], qa2.x, B0); ffma2(acc[4][1], qa2.x, B1);
            ffma2(acc[4][2], qa2.x, B2); ffma2(acc[4][3], qa2.x, B3);
            ffma2(acc[5][0], qa2.y, B0); ffma2(acc[5][1], qa2.y, B1);
            ffma2(acc[5][2], qa2.y, B2); ffma2(acc[5][3], qa2.y, B3);
            ffma2(acc[6][0], qa3.x, B0); ffma2(acc[6][1], qa3.x, B1);
            ffma2(acc[6][2], qa3.x, B2); ffma2(acc[6][3], qa3.x, B3);
            ffma2(acc[7][0], qa3.y, B0); ffma2(acc[7][1], qa3.y, B1);
            ffma2(acc[7][2], qa3.y, B2); ffma2(acc[7][3], qa3.y, B3);
        }
        // this warp is done reading wS[s]
        if (lane == 0) { if (s == 0) mbar_arrive(e0); else mbar_arrive(e1); }
        if (kt + 1 < NT) {
            float* xn = xd + (s ^ 1) * (BK1 * XDP);
            float v[8] = {xs0.x, xs0.y, xs0.z, xs0.w, xs1.x, xs1.y, xs1.z, xs1.w};
            #pragma unroll
            for (int i = 0; i < 8; ++i)
                *(float2*)(xn + (xk + i) * XDP + 2 * xr) = make_float2(v[i], v[i]);
            __syncwarp();
        }
    }

    // epilogue: +bias (packed), sumsq butterfly, store P rows + g_sq
    u64 bp0 = *(const u64*)(bias + nA);
    u64 bp1 = *(const u64*)(bias + nA + 2);
    u64 bp2 = *(const u64*)(bias + nB);
    u64 bp3 = *(const u64*)(bias + nB + 2);
    #pragma unroll
    for (int m = 0; m < 8; ++m) {
        fadd2(acc[m][0], bp0); fadd2(acc[m][1], bp1);
        fadd2(acc[m][2], bp2); fadd2(acc[m][3], bp3);
        u64 sp = 0ull;
        ffma2(sp, acc[m][0], acc[m][0]); ffma2(sp, acc[m][1], acc[m][1]);
        ffma2(sp, acc[m][2], acc[m][2]); ffma2(sp, acc[m][3], acc[m][3]);
        float lo, hi; unpack2(sp, lo, hi);
        float s = lo + hi;
        #pragma unroll
        for (int o = 16; o; o >>= 1) s += __shfl_xor_sync(0xffffffffu, s, o);
        int row = t0 + mb + m;
        u64* pr = (u64*)(g_P + (size_t)row * ED);
        pr[nA / 2]     = acc[m][0];
        pr[nA / 2 + 1] = acc[m][1];
        pr[nB / 2]     = acc[m][2];
        pr[nB / 2 + 1] = acc[m][3];
        if (lane == 0) g_sq[row] = s;
    }
}

// ---------------- K2: sims + top-2 + softmax (round-4 loop + pipeline) ----------------
#define C2BYTES (BK2 * NE * 4)

__global__ __launch_bounds__(256, 2)
void k2_kernel(float* __restrict__ out, int ntok) {
    extern __shared__ __align__(16) float sm2[];
    float* PsT = sm2;                      // [ED][PSTP] : P transposed [k][m]
    float* ct  = sm2 + ED * PSTP;          // [2][BK2][NE] center tiles
    __shared__ __align__(8) u64 mbars[4];

    const int tid = threadIdx.x;
    const int w = tid >> 5, lane = tid & 31;
    const int t0 = blockIdx.x * TT;
    const int mb = (w >> 1) * 8;
    const int nh = (w & 1) * 256;
    const int nA = nh + lane * 4, nB = nh + 128 + lane * 4;

    u32 ct_u32 = (u32)__cvta_generic_to_shared(ct);
    u32 f0 = (u32)__cvta_generic_to_shared(&mbars[0]);
    u32 f1 = f0 + 8, e0 = f0 + 16, e1 = f0 + 24;
    int pf0 = 0, pf1 = 0, pe0 = 0, pe1 = 0;

    if (tid == 0) {
        mbar_init(f0, 1); mbar_init(f1, 1);
        mbar_init(e0, 8); mbar_init(e1, 8);
    }
    __syncthreads();
    if (tid == 0) { mbar_expect_tx(f0, C2BYTES); bulk_g2s(ct_u32, g_cnT, C2BYTES, f0); }

    // transpose P tile into PsT (overlaps with bulk copy)
    const int pr = tid >> 3, pcq = (tid & 7) * 4;
    #pragma unroll
    for (int j = 0; j < 8; ++j) {
        int c = pcq + 32 * j;
        float4 v = *(const float4*)(g_P + (size_t)(t0 + pr) * ED + c);
        PsT[(c + 0) * PSTP + pr] = v.x;
        PsT[(c + 1) * PSTP + pr] = v.y;
        PsT[(c + 2) * PSTP + pr] = v.z;
        PsT[(c + 3) * PSTP + pr] = v.w;
    }
    __syncthreads();   // PsT visible to all warps

    u64 acc[4][8];
    #pragma unroll
    for (int p = 0; p < 4; ++p)
        #pragma unroll
        for (int j = 0; j < 8; ++j) acc[p][j] = 0ull;

    const int NT = ED / BK2;
    for (int kt = 0; kt < NT; ++kt) {
        const int s = kt & 1;
        if (kt + 1 < NT && tid == 0) {
            if (s == 0) {
                if (kt) { mbar_wait(e1, pe1); pe1 ^= 1; }
                mbar_expect_tx(f1, C2BYTES);
                bulk_g2s(ct_u32 + C2BYTES, g_cnT + (size_t)(kt + 1) * BK2 * NE, C2BYTES, f1);
            } else {
                mbar_wait(e0, pe0); pe0 ^= 1;
                mbar_expect_tx(f0, C2BYTES);
                bulk_g2s(ct_u32, g_cnT + (size_t)(kt + 1) * BK2 * NE, C2BYTES, f0);
            }
        }
        if (s == 0) { mbar_wait(f0, pf0); pf0 ^= 1; }
        else        { mbar_wait(f1, pf1); pf1 ^= 1; }

        const float* cb = ct + s * (BK2 * NE);
        #pragma unroll
        for (int k = 0; k < BK2; ++k) {
            const int kk = kt * BK2 + k;
            const u64* ap = (const u64*)(PsT + kk * PSTP + mb);
            u64 a0 = ap[0], a1 = ap[1], a2 = ap[2], a3 = ap[3];
            float4 b0 = *(const float4*)(cb + k * NE + nA);
            float4 b1 = *(const float4*)(cb + k * NE + nB);
            u64 bb0 = pack2(b0.x, b0.x), bb1 = pack2(b0.y, b0.y);
            u64 bb2 = pack2(b0.z, b0.z), bb3 = pack2(b0.w, b0.w);
            u64 bb4 = pack2(b1.x, b1.x), bb5 = pack2(b1.y, b1.y);
            u64 bb6 = pack2(b1.z, b1.z), bb7 = pack2(b1.w, b1.w);
            ffma2(acc[0][0], a0, bb0); ffma2(acc[0][1], a0, bb1);
            ffma2(acc[0][2], a0, bb2); ffma2(acc[0][3], a0, bb3);
            ffma2(acc[0][4], a0, bb4); ffma2(acc[0][5], a0, bb5);
            ffma2(acc[0][6], a0, bb6); ffma2(acc[0][7], a0, bb7);
            ffma2(acc[1][0], a1, bb0); ffma2(acc[1][1], a1, bb1);
            ffma2(acc[1][2], a1, bb2); ffma2(acc[1][3], a1, bb3);
            ffma2(acc[1][4], a1, bb4); ffma2(acc[1][5], a1, bb5);
            ffma2(acc[1][6], a1, bb6); ffma2(acc[1][7], a1, bb7);
            ffma2(acc[2][0], a2, bb0); ffma2(acc[2][1], a2, bb1);
            ffma2(acc[2][2], a2, bb2); ffma2(acc[2][3], a2, bb3);
            ffma2(acc[2][4], a2, bb4); ffma2(acc[2][5], a2, bb5);
            ffma2(acc[2][6], a2, bb6); ffma2(acc[2][7], a2, bb7);
            ffma2(acc[3][0], a3, bb0); ffma2(acc[3][1], a3, bb1);
            ffma2(acc[3][2], a3, bb2); ffma2(acc[3][3], a3, bb3);
            ffma2(acc[3][4], a3, bb4); ffma2(acc[3][5], a3, bb5);
            ffma2(acc[3][6], a3, bb6); ffma2(acc[3][7], a3, bb7);
        }
        if (lane == 0) { if (s == 0) mbar_arrive(e0); else mbar_arrive(e1); }
    }

    // per-thread -> per-warp top-2 over this warp's 256-expert half
    float v1[8], v2[8]; int i1[8], i2[8];
    #pragma unroll
    for (int r = 0; r < 8; ++r) { v1[r] = -INFINITY; v2[r] = -INFINITY; i1[r] = 0; i2[r] = 0; }
    #pragma unroll
    for (int p = 0; p < 4; ++p)
        #pragma unroll
        for (int j = 0; j < 8; ++j) {
            float lo, hi; unpack2(acc[p][j], lo, hi);
            int gi = (j < 4) ? (nA + j) : (nB + j - 4);
            upd(lo, gi, v1[2 * p],     i1[2 * p],     v2[2 * p],     i2[2 * p]);
            upd(hi, gi, v1[2 * p + 1], i1[2 * p + 1], v2[2 * p + 1], i2[2 * p + 1]);
        }
    #pragma unroll
    for (int r = 0; r < 8; ++r)
        #pragma unroll
        for (int o = 16; o; o >>= 1) {
            float o1 = __shfl_xor_sync(0xffffffffu, v1[r], o);
            int  oi1 = __shfl_xor_sync(0xffffffffu, i1[r], o);
            float o2 = __shfl_xor_sync(0xffffffffu, v2[r], o);
            int  oi2 = __shfl_xor_sync(0xffffffffu, i2[r], o);
            upd(o1, oi1, v1[r], i1[r], v2[r], i2[r]);
            upd(o2, oi2, v1[r], i1[r], v2[r], i2[r]);
        }

    __syncthreads();   // all warps past all ct reads before reusing ct as merge buffer
    float4* mg = (float4*)ct;              // [TT][2]
    if (lane == 0) {
        #pragma unroll
        for (int r = 0; r < 8; ++r)
            mg[(mb + r) * 2 + (w & 1)] =
                make_float4(v1[r], __int_as_float(i1[r]), v2[r], __int_as_float(i2[r]));
    }
    __syncthreads();

    if (tid < TT) {
        float4 A = mg[tid * 2 + 0];
        float4 B = mg[tid * 2 + 1];
        float V1 = A.x, V2 = A.z;
        int I1 = __float_as_int(A.y), I2 = __float_as_int(A.w);
        upd(B.x, __float_as_int(B.y), V1, I1, V2, I2);
        upd(B.z, __float_as_int(B.w), V1, I1, V2, I2);
        int token = t0 + tid;
        float inv = 1.f / fmaxf(sqrtf(g_sq[token]), 1e-12f);
        float e2 = expf((V2 - V1) * inv);
        float den = 1.f + e2;
        out[2 * token]     = 1.f / den;
        out[2 * token + 1] = e2 / den;
        float* oi = out + 2 * (size_t)ntok;
        oi[2 * token]     = (float)I1;
        oi[2 * token + 1] = (float)I2;
    }
}

extern "C" void kernel_launch(void* const* d_in, const int* in_sizes, int n_in,
                              void* d_out, int out_size) {
    const float* x = (const float*)d_in[0];
    const float* W = (const float*)d_in[1];
    const float* b = (const float*)d_in[2];
    const float* c = (const float*)d_in[3];
    int ntok = in_sizes[0] / IN_DIM;   // 131072

    cnorm_kernel<<<NE, ED>>>(c);
    prep_wt_kernel<<<dim3(IN_DIM / 32, ED / 32), dim3(32, 8)>>>(W);

    int smem1 = (2 * BK1 * XDP + 2 * BK1 * ED) * (int)sizeof(float);   // 99328 B
    cudaFuncSetAttribute(k1_kernel, cudaFuncAttributeMaxDynamicSharedMemorySize, smem1);
    k1_kernel<<<ntok / 64, 256, smem1>>>(x, b);

    int smem2 = (ED * PSTP + 2 * BK2 * NE) * (int)sizeof(float);       // 100352 B
    cudaFuncSetAttribute(k2_kernel, cudaFuncAttributeMaxDynamicSharedMemorySize, smem2);
    k2_kernel<<<ntok / TT, 256, smem2>>>((float*)d_out, ntok);
}

// round 9
// speedup vs baseline: 1.4104x; 1.1328x over previous
#include <cuda_runtime.h>
#include <math.h>
#include <stdint.h>

#define IN_DIM 1024
#define ED 256
#define NE 512
#define NTOK_MAX 131072
#define TT 32
#define XTP 68
#define PSTP 36
#define BK1 32
#define BK2 16

typedef unsigned long long u64;
typedef uint32_t u32;

__device__ __align__(16) float g_WT[IN_DIM * ED];     // W transposed [k][n]
__device__ __align__(16) float g_cnT[ED * NE];        // normalized centers [k][e]
__device__ __align__(16) float g_P[(size_t)NTOK_MAX * ED];
__device__ float g_sq[NTOK_MAX];

static __device__ __forceinline__ u64 pack2(float lo, float hi) {
    u64 r; asm("mov.b64 %0, {%1, %2};" : "=l"(r) : "f"(lo), "f"(hi)); return r;
}
static __device__ __forceinline__ void unpack2(u64 v, float& lo, float& hi) {
    asm("mov.b64 {%0, %1}, %2;" : "=f"(lo), "=f"(hi) : "l"(v));
}
static __device__ __forceinline__ void ffma2(u64& d, u64 a, u64 b) {
    asm("fma.rn.f32x2 %0, %1, %2, %0;" : "+l"(d) : "l"(a), "l"(b));
}
static __device__ __forceinline__ void fadd2(u64& d, u64 a) {
    asm("add.rn.f32x2 %0, %0, %1;" : "+l"(d) : "l"(a));
}

// ---- bulk async copy + mbarrier helpers ----
static __device__ __forceinline__ void mbar_init(u32 mbar, u32 cnt) {
    asm volatile("mbarrier.init.shared.b64 [%0], %1;" :: "r"(mbar), "r"(cnt) : "memory");
}
static __device__ __forceinline__ void mbar_expect_tx(u32 mbar, u32 bytes) {
    asm volatile("mbarrier.arrive.expect_tx.shared.b64 _, [%0], %1;" :: "r"(mbar), "r"(bytes) : "memory");
}
static __device__ __forceinline__ void bulk_g2s(u32 dst, const float* src,
                                                u32 bytes, u32 mbar) {
    asm volatile("cp.async.bulk.shared::cta.global.mbarrier::complete_tx::bytes [%0], [%1], %2, [%3];"
                 :: "r"(dst), "l"(src), "r"(bytes), "r"(mbar) : "memory");
}
static __device__ __forceinline__ void mbar_wait(u32 mbar, u32 parity) {
    u32 done;
    asm volatile(
        "{\n\t.reg .pred p;\n\t"
        "mbarrier.try_wait.parity.acquire.cta.shared::cta.b64 p, [%1], %2;\n\t"
        "selp.b32 %0, 1, 0, p;\n\t}"
        : "=r"(done) : "r"(mbar), "r"(parity) : "memory");
    if (!done) {
        asm volatile(
            "{\n\t.reg .pred P1;\n\t"
            "WL_%=:\n\t"
            "mbarrier.try_wait.parity.acquire.cta.shared::cta.b64 P1, [%0], %1, 0x989680;\n\t"
            "@P1 bra.uni WD_%=;\n\t"
            "bra.uni WL_%=;\n\t"
            "WD_%=:\n\t}"
            :: "r"(mbar), "r"(parity) : "memory");
    }
}

static __device__ __forceinline__ void upd(float v, int i,
                                           float& v1, int& i1, float& v2, int& i2) {
    if (v > v1 || (v == v1 && i < i1)) { v2 = v1; i2 = i1; v1 = v; i1 = i; }
    else if (v > v2 || (v == v2 && i < i2)) { v2 = v; i2 = i; }
}

// ---------------- prep: normalize centers -> g_cnT [k][e] ----------------
__global__ void cnorm_kernel(const float* __restrict__ centers) {
    __shared__ float ws[8];
    int e = blockIdx.x, t = threadIdx.x;
    float v = centers[e * ED + t];
    float s = v * v;
    #pragma unroll
    for (int o = 16; o; o >>= 1) s += __shfl_xor_sync(0xffffffffu, s, o);
    if ((t & 31) == 0) ws[t >> 5] = s;
    __syncthreads();
    float tot = 0.f;
    #pragma unroll
    for (int i = 0; i < 8; ++i) tot += ws[i];
    float norm = fmaxf(sqrtf(tot), 1e-12f);
    g_cnT[t * NE + e] = v / norm;
}

// ---------------- prep: transpose W [n][k] -> g_WT [k][n] ----------------
__global__ void prep_wt_kernel(const float* __restrict__ W) {
    __shared__ float t[32][33];
    int bx = blockIdx.x * 32;
    int by = blockIdx.y * 32;
    int x = threadIdx.x, y = threadIdx.y;
    #pragma unroll
    for (int j = 0; j < 32; j += 8)
        t[y + j][x] = W[(size_t)(by + y + j) * IN_DIM + bx + x];
    __syncthreads();
    #pragma unroll
    for (int j = 0; j < 32; j += 8)
        g_WT[(size_t)(bx + y + j) * ED + by + x] = t[x][y + j];
}

// ---------------- K1: P = x @ W^T + b  (16m x 4n per thread, m-pair accs) ----------------
#define W1BYTES (BK1 * ED * 4)

__global__ __launch_bounds__(256, 2)
void k1_kernel(const float* __restrict__ x, const float* __restrict__ bias) {
    extern __shared__ __align__(16) float sm1[];
    float* xT = sm1;                       // [2][BK1][XTP]  x transposed (non-dup), k-major
    float* wS = sm1 + 2 * BK1 * XTP;       // [2][BK1][ED]   W tile, k-major
    __shared__ __align__(8) u64 mbars[2];
    __shared__ float sq_sm[64][2];

    const int tid = threadIdx.x;
    const int w = tid >> 5, lane = tid & 31;
    const int t0 = blockIdx.x * 64;
    const int mb = (w & 3) * 16;           // 16 rows per warp
    const int nc = (w >> 2) * 128 + lane * 4;  // 4 cols per lane, 128-col half per warp group

    const int xr = tid >> 2, xk = (tid & 3) * 8;
    const float* xp = x + (size_t)(t0 + xr) * IN_DIM + xk;

    u32 wS_u32 = (u32)__cvta_generic_to_shared(wS);
    u32 mb0 = (u32)__cvta_generic_to_shared(&mbars[0]);
    u32 mb1 = mb0 + 8;
    int ph0 = 0, ph1 = 0;

    u64 acc[8][4];
    #pragma unroll
    for (int m = 0; m < 8; ++m)
        #pragma unroll
        for (int p = 0; p < 4; ++p) acc[m][p] = 0ull;

    if (tid == 0) { mbar_init(mb0, 1); mbar_init(mb1, 1); }
    __syncthreads();

    if (tid == 0) { mbar_expect_tx(mb0, W1BYTES); bulk_g2s(wS_u32, g_WT, W1BYTES, mb0); }
    float4 xs0 = *(const float4*)xp;
    float4 xs1 = *(const float4*)(xp + 4);
    {
        float v[8] = {xs0.x, xs0.y, xs0.z, xs0.w, xs1.x, xs1.y, xs1.z, xs1.w};
        #pragma unroll
        for (int i = 0; i < 8; ++i)
            xT[(xk + i) * XTP + xr] = v[i];
    }
    mbar_wait(mb0, ph0); ph0 ^= 1;
    __syncthreads();

    const int NT = IN_DIM / BK1;
    for (int kt = 0; kt < NT; ++kt) {
        const int buf = kt & 1;
        const float* xb = xT + buf * (BK1 * XTP);
        const float* wb = wS + buf * (BK1 * ED);
        if (kt + 1 < NT) {
            if (tid == 0) {
                u32 m = buf ? mb0 : mb1;
                mbar_expect_tx(m, W1BYTES);
                bulk_g2s(wS_u32 + (u32)((buf ^ 1) * W1BYTES),
                         g_WT + (size_t)(kt + 1) * BK1 * ED, W1BYTES, m);
            }
            xs0 = *(const float4*)(xp + (kt + 1) * BK1);
            xs1 = *(const float4*)(xp + (kt + 1) * BK1 + 4);
        }
        #pragma unroll
        for (int k = 0; k < BK1; ++k) {
            const ulonglong2* ap = (const ulonglong2*)(xb + k * XTP + mb);
            ulonglong2 qa0 = ap[0], qa1 = ap[1], qa2 = ap[2], qa3 = ap[3];
            float4 b = *(const float4*)(wb + k * ED + nc);
            u64 B0 = pack2(b.x, b.x), B1 = pack2(b.y, b.y);
            u64 B2 = pack2(b.z, b.z), B3 = pack2(b.w, b.w);
            ffma2(acc[0][0], qa0.x, B0); ffma2(acc[0][1], qa0.x, B1);
            ffma2(acc[0][2], qa0.x, B2); ffma2(acc[0][3], qa0.x, B3);
            ffma2(acc[1][0], qa0.y, B0); ffma2(acc[1][1], qa0.y, B1);
            ffma2(acc[1][2], qa0.y, B2); ffma2(acc[1][3], qa0.y, B3);
            ffma2(acc[2][0], qa1.x, B0); ffma2(acc[2][1], qa1.x, B1);
            ffma2(acc[2][2], qa1.x, B2); ffma2(acc[2][3], qa1.x, B3);
            ffma2(acc[3][0], qa1.y, B0); ffma2(acc[3][1], qa1.y, B1);
            ffma2(acc[3][2], qa1.y, B2); ffma2(acc[3][3], qa1.y, B3);
            ffma2(acc[4][0], qa2.x, B0); ffma2(acc[4][1], qa2.x, B1);
            ffma2(acc[4][2], qa2.x, B2); ffma2(acc[4][3], qa2.x, B3);
            ffma2(acc[5][0], qa2.y, B0); ffma2(acc[5][1], qa2.y, B1);
            ffma2(acc[5][2], qa2.y, B2); ffma2(acc[5][3], qa2.y, B3);
            ffma2(acc[6][0], qa3.x, B0); ffma2(acc[6][1], qa3.x, B1);
            ffma2(acc[6][2], qa3.x, B2); ffma2(acc[6][3], qa3.x, B3);
            ffma2(acc[7][0], qa3.y, B0); ffma2(acc[7][1], qa3.y, B1);
            ffma2(acc[7][2], qa3.y, B2); ffma2(acc[7][3], qa3.y, B3);
        }
        if (kt + 1 < NT) {
            float* xn = xT + (buf ^ 1) * (BK1 * XTP);
            float v[8] = {xs0.x, xs0.y, xs0.z, xs0.w, xs1.x, xs1.y, xs1.z, xs1.w};
            #pragma unroll
            for (int i = 0; i < 8; ++i)
                xn[(xk + i) * XTP + xr] = v[i];
            if (buf) { mbar_wait(mb0, ph0); ph0 ^= 1; }
            else     { mbar_wait(mb1, ph1); ph1 ^= 1; }
        }
        __syncthreads();
    }

    // epilogue: +bias (dup-packed), per-pair sumsq butterfly, store P + g_sq
    float4 b4 = *(const float4*)(bias + nc);
    u64 bp[4];
    bp[0] = pack2(b4.x, b4.x); bp[1] = pack2(b4.y, b4.y);
    bp[2] = pack2(b4.z, b4.z); bp[3] = pack2(b4.w, b4.w);

    u64 sp[8];
    #pragma unroll
    for (int m = 0; m < 8; ++m) {
        sp[m] = 0ull;
        #pragma unroll
        for (int j = 0; j < 4; ++j) {
            fadd2(acc[m][j], bp[j]);
            ffma2(sp[m], acc[m][j], acc[m][j]);
        }
    }
    #pragma unroll
    for (int m = 0; m < 8; ++m)
        #pragma unroll
        for (int o = 16; o; o >>= 1) {
            u64 t = __shfl_xor_sync(0xffffffffu, sp[m], o);
            fadd2(sp[m], t);
        }

    #pragma unroll
    for (int m = 0; m < 8; ++m) {
        float lo[4], hi[4];
        #pragma unroll
        for (int j = 0; j < 4; ++j) unpack2(acc[m][j], lo[j], hi[j]);
        int r = t0 + mb + 2 * m;
        *(float4*)(g_P + (size_t)r * ED + nc)        = make_float4(lo[0], lo[1], lo[2], lo[3]);
        *(float4*)(g_P + (size_t)(r + 1) * ED + nc)  = make_float4(hi[0], hi[1], hi[2], hi[3]);
    }
    if (lane == 0) {
        #pragma unroll
        for (int m = 0; m < 8; ++m) {
            float se, so; unpack2(sp[m], se, so);
            sq_sm[mb + 2 * m][w >> 2]     = se;
            sq_sm[mb + 2 * m + 1][w >> 2] = so;
        }
    }
    __syncthreads();
    if (tid < 64) g_sq[t0 + tid] = sq_sm[tid][0] + sq_sm[tid][1];
}

// ---------------- K2: sims + top-2 + softmax (16 tokens x 128 experts per warp) ----------------
#define C2BYTES (BK2 * NE * 4)

__global__ __launch_bounds__(256, 2)
void k2_kernel(float* __restrict__ out, int ntok) {
    extern __shared__ __align__(16) float sm2[];
    float* PsT = sm2;                      // [ED][PSTP] : P transposed [k][m]
    float* ct  = sm2 + ED * PSTP;          // [2][BK2][NE] center tiles
    __shared__ __align__(8) u64 mbars[2];

    const int tid = threadIdx.x;
    const int w = tid >> 5, lane = tid & 31;
    const int t0 = blockIdx.x * TT;
    const int g = w >> 2, h = w & 3;
    const int mb = g * 16;                 // 16 tokens per warp
    const int nc = h * 128 + lane * 4;     // 4 experts per lane within 128-expert group

    u32 ct_u32 = (u32)__cvta_generic_to_shared(ct);
    u32 mb0 = (u32)__cvta_generic_to_shared(&mbars[0]);
    u32 mb1 = mb0 + 8;
    int ph0 = 0, ph1 = 0;

    if (tid == 0) { mbar_init(mb0, 1); mbar_init(mb1, 1); }
    __syncthreads();
    if (tid == 0) { mbar_expect_tx(mb0, C2BYTES); bulk_g2s(ct_u32, g_cnT, C2BYTES, mb0); }

    // transpose P tile into PsT (overlaps with bulk copy)
    const int pr = tid >> 3, pcq = (tid & 7) * 4;
    #pragma unroll
    for (int j = 0; j < 8; ++j) {
        int c = pcq + 32 * j;
        float4 v = *(const float4*)(g_P + (size_t)(t0 + pr) * ED + c);
        PsT[(c + 0) * PSTP + pr] = v.x;
        PsT[(c + 1) * PSTP + pr] = v.y;
        PsT[(c + 2) * PSTP + pr] = v.z;
        PsT[(c + 3) * PSTP + pr] = v.w;
    }
    mbar_wait(mb0, ph0); ph0 ^= 1;
    __syncthreads();

    u64 acc[8][4];
    #pragma unroll
    for (int m = 0; m < 8; ++m)
        #pragma unroll
        for (int p = 0; p < 4; ++p) acc[m][p] = 0ull;

    const int NT = ED / BK2;
    for (int kt = 0; kt < NT; ++kt) {
        const int buf = kt & 1;
        const float* cb = ct + buf * (BK2 * NE);
        if (kt + 1 < NT && tid == 0) {
            u32 m = buf ? mb0 : mb1;
            mbar_expect_tx(m, C2BYTES);
            bulk_g2s(ct_u32 + (u32)((buf ^ 1) * C2BYTES),
                     g_cnT + (size_t)(kt + 1) * BK2 * NE, C2BYTES, m);
        }
        #pragma unroll
        for (int k = 0; k < BK2; ++k) {
            const int kk = kt * BK2 + k;
            const ulonglong2* ap = (const ulonglong2*)(PsT + kk * PSTP + mb);
            ulonglong2 qa0 = ap[0], qa1 = ap[1], qa2 = ap[2], qa3 = ap[3];
            float4 b = *(const float4*)(cb + k * NE + nc);
            u64 B0 = pack2(b.x, b.x), B1 = pack2(b.y, b.y);
            u64 B2 = pack2(b.z, b.z), B3 = pack2(b.w, b.w);
            ffma2(acc[0][0], qa0.x, B0); ffma2(acc[0][1], qa0.x, B1);
            ffma2(acc[0][2], qa0.x, B2); ffma2(acc[0][3], qa0.x, B3);
            ffma2(acc[1][0], qa0.y, B0); ffma2(acc[1][1], qa0.y, B1);
            ffma2(acc[1][2], qa0.y, B2); ffma2(acc[1][3], qa0.y, B3);
            ffma2(acc[2][0], qa1.x, B0); ffma2(acc[2][1], qa1.x, B1);
            ffma2(acc[2][2], qa1.x, B2); ffma2(acc[2][3], qa1.x, B3);
            ffma2(acc[3][0], qa1.y, B0); ffma2(acc[3][1], qa1.y, B1);
            ffma2(acc[3][2], qa1.y, B2); ffma2(acc[3][3], qa1.y, B3);
            ffma2(acc[4][0], qa2.x, B0); ffma2(acc[4][1], qa2.x, B1);
            ffma2(acc[4][2], qa2.x, B2); ffma2(acc[4][3], qa2.x, B3);
            ffma2(acc[5][0], qa2.y, B0); ffma2(acc[5][1], qa2.y, B1);
            ffma2(acc[5][2], qa2.y, B2); ffma2(acc[5][3], qa2.y, B3);
            ffma2(acc[6][0], qa3.x, B0); ffma2(acc[6][1], qa3.x, B1);
            ffma2(acc[6][2], qa3.x, B2); ffma2(acc[6][3], qa3.x, B3);
            ffma2(acc[7][0], qa3.y, B0); ffma2(acc[7][1], qa3.y, B1);
            ffma2(acc[7][2], qa3.y, B2); ffma2(acc[7][3], qa3.y, B3);
        }
        if (kt + 1 < NT) {
            if (buf) { mbar_wait(mb0, ph0); ph0 ^= 1; }
            else     { mbar_wait(mb1, ph1); ph1 ^= 1; }
        }
        __syncthreads();
    }

    // per-thread top-2 (16 token slots x 4 experts), then butterfly over 128-expert group
    float v1[16], v2[16]; int i1[16], i2[16];
    #pragma unroll
    for (int s = 0; s < 16; ++s) { v1[s] = -INFINITY; v2[s] = -INFINITY; i1[s] = 0; i2[s] = 0; }
    #pragma unroll
    for (int m = 0; m < 8; ++m)
        #pragma unroll
        for (int j = 0; j < 4; ++j) {
            float lo, hi; unpack2(acc[m][j], lo, hi);
            int gi = nc + j;
            upd(lo, gi, v1[2 * m],     i1[2 * m],     v2[2 * m],     i2[2 * m]);
            upd(hi, gi, v1[2 * m + 1], i1[2 * m + 1], v2[2 * m + 1], i2[2 * m + 1]);
        }
    #pragma unroll
    for (int s = 0; s < 16; ++s)
        #pragma unroll
        for (int o = 16; o; o >>= 1) {
            float o1 = __shfl_xor_sync(0xffffffffu, v1[s], o);
            int  oi1 = __shfl_xor_sync(0xffffffffu, i1[s], o);
            float o2 = __shfl_xor_sync(0xffffffffu, v2[s], o);
            int  oi2 = __shfl_xor_sync(0xffffffffu, i2[s], o);
            upd(o1, oi1, v1[s], i1[s], v2[s], i2[s]);
            upd(o2, oi2, v1[s], i1[s], v2[s], i2[s]);
        }

    // merge 4 expert groups via smem (ct reusable: loop ended with __syncthreads)
    float4* mg = (float4*)ct;              // [TT][4]
    if (lane == 0) {
        #pragma unroll
        for (int s = 0; s < 16; ++s)
            mg[(mb + s) * 4 + h] =
                make_float4(v1[s], __int_as_float(i1[s]), v2[s], __int_as_float(i2[s]));
    }
    __syncthreads();

    if (tid < TT) {
        float4 A = mg[tid * 4 + 0];
        float V1 = A.x, V2 = A.z;
        int I1 = __float_as_int(A.y), I2 = __float_as_int(A.w);
        #pragma unroll
        for (int hh = 1; hh < 4; ++hh) {
            float4 Bq = mg[tid * 4 + hh];
            upd(Bq.x, __float_as_int(Bq.y), V1, I1, V2, I2);
            upd(Bq.z, __float_as_int(Bq.w), V1, I1, V2, I2);
        }
        int token = t0 + tid;
        float inv = 1.f / fmaxf(sqrtf(g_sq[token]), 1e-12f);
        float e2 = expf((V2 - V1) * inv);
        float den = 1.f + e2;
        out[2 * token]     = 1.f / den;
        out[2 * token + 1] = e2 / den;
        float* oi = out + 2 * (size_t)ntok;
        oi[2 * token]     = (float)I1;
        oi[2 * token + 1] = (float)I2;
    }
}

extern "C" void kernel_launch(void* const* d_in, const int* in_sizes, int n_in,
                              void* d_out, int out_size) {
    const float* x = (const float*)d_in[0];
    const float* W = (const float*)d_in[1];
    const float* b = (const float*)d_in[2];
    const float* c = (const float*)d_in[3];
    int ntok = in_sizes[0] / IN_DIM;   // 131072

    cnorm_kernel<<<NE, ED>>>(c);
    prep_wt_kernel<<<dim3(IN_DIM / 32, ED / 32), dim3(32, 8)>>>(W);

    int smem1 = (2 * BK1 * XTP + 2 * BK1 * ED) * (int)sizeof(float);   // 82944 B
    cudaFuncSetAttribute(k1_kernel, cudaFuncAttributeMaxDynamicSharedMemorySize, smem1);
    k1_kernel<<<ntok / 64, 256, smem1>>>(x, b);

    int smem2 = (ED * PSTP + 2 * BK2 * NE) * (int)sizeof(float);       // 102400 B
    cudaFuncSetAttribute(k2_kernel, cudaFuncAttributeMaxDynamicSharedMemorySize, smem2);
    k2_kernel<<<ntok / TT, 256, smem2>>>((float*)d_out, ntok);
}

// round 10
// speedup vs baseline: 1.4814x; 1.0503x over previous
#include <cuda_runtime.h>
#include <math.h>
#include <stdint.h>

#define IN_DIM 1024
#define ED 256
#define NE 512
#define NTOK_MAX 131072
#define TT 32
#define XTP 68
#define PSTP 34
#define BK1 32
#define BK2 16

typedef unsigned long long u64;
typedef uint32_t u32;

__device__ __align__(16) float g_WT[IN_DIM * ED];     // W transposed [k][n]
__device__ __align__(16) float g_cnT[ED * NE];        // normalized centers [k][e]
__device__ __align__(16) float g_P[(size_t)NTOK_MAX * ED];
__device__ float g_sq[NTOK_MAX];

static __device__ __forceinline__ u64 pack2(float lo, float hi) {
    u64 r; asm("mov.b64 %0, {%1, %2};" : "=l"(r) : "f"(lo), "f"(hi)); return r;
}
static __device__ __forceinline__ void unpack2(u64 v, float& lo, float& hi) {
    asm("mov.b64 {%0, %1}, %2;" : "=f"(lo), "=f"(hi) : "l"(v));
}
static __device__ __forceinline__ void ffma2(u64& d, u64 a, u64 b) {
    asm("fma.rn.f32x2 %0, %1, %2, %0;" : "+l"(d) : "l"(a), "l"(b));
}
static __device__ __forceinline__ void fadd2(u64& d, u64 a) {
    asm("add.rn.f32x2 %0, %0, %1;" : "+l"(d) : "l"(a));
}

// ---- bulk async copy + mbarrier helpers ----
static __device__ __forceinline__ void mbar_init(u32 mbar, u32 cnt) {
    asm volatile("mbarrier.init.shared.b64 [%0], %1;" :: "r"(mbar), "r"(cnt) : "memory");
}
static __device__ __forceinline__ void mbar_expect_tx(u32 mbar, u32 bytes) {
    asm volatile("mbarrier.arrive.expect_tx.shared.b64 _, [%0], %1;" :: "r"(mbar), "r"(bytes) : "memory");
}
static __device__ __forceinline__ void bulk_g2s(u32 dst, const float* src,
                                                u32 bytes, u32 mbar) {
    asm volatile("cp.async.bulk.shared::cta.global.mbarrier::complete_tx::bytes [%0], [%1], %2, [%3];"
                 :: "r"(dst), "l"(src), "r"(bytes), "r"(mbar) : "memory");
}
static __device__ __forceinline__ void mbar_wait(u32 mbar, u32 parity) {
    u32 done;
    asm volatile(
        "{\n\t.reg .pred p;\n\t"
        "mbarrier.try_wait.parity.acquire.cta.shared::cta.b64 p, [%1], %2;\n\t"
        "selp.b32 %0, 1, 0, p;\n\t}"
        : "=r"(done) : "r"(mbar), "r"(parity) : "memory");
    if (!done) {
        asm volatile(
            "{\n\t.reg .pred P1;\n\t"
            "WL_%=:\n\t"
            "mbarrier.try_wait.parity.acquire.cta.shared::cta.b64 P1, [%0], %1, 0x989680;\n\t"
            "@P1 bra.uni WD_%=;\n\t"
            "bra.uni WL_%=;\n\t"
            "WD_%=:\n\t}"
            :: "r"(mbar), "r"(parity) : "memory");
    }
}

static __device__ __forceinline__ void upd(float v, int i,
                                           float& v1, int& i1, float& v2, int& i2) {
    if (v > v1 || (v == v1 && i < i1)) { v2 = v1; i2 = i1; v1 = v; i1 = i; }
    else if (v > v2 || (v == v2 && i < i2)) { v2 = v; i2 = i; }
}

// ---------------- prep: normalize centers -> g_cnT [k][e] ----------------
__global__ void cnorm_kernel(const float* __restrict__ centers) {
    __shared__ float ws[8];
    int e = blockIdx.x, t = threadIdx.x;
    float v = centers[e * ED + t];
    float s = v * v;
    #pragma unroll
    for (int o = 16; o; o >>= 1) s += __shfl_xor_sync(0xffffffffu, s, o);
    if ((t & 31) == 0) ws[t >> 5] = s;
    __syncthreads();
    float tot = 0.f;
    #pragma unroll
    for (int i = 0; i < 8; ++i) tot += ws[i];
    float norm = fmaxf(sqrtf(tot), 1e-12f);
    g_cnT[t * NE + e] = v / norm;
}

// ---------------- prep: transpose W [n][k] -> g_WT [k][n] ----------------
__global__ void prep_wt_kernel(const float* __restrict__ W) {
    __shared__ float t[32][33];
    int bx = blockIdx.x * 32;
    int by = blockIdx.y * 32;
    int x = threadIdx.x, y = threadIdx.y;
    #pragma unroll
    for (int j = 0; j < 32; j += 8)
        t[y + j][x] = W[(size_t)(by + y + j) * IN_DIM + bx + x];
    __syncthreads();
    #pragma unroll
    for (int j = 0; j < 32; j += 8)
        g_WT[(size_t)(bx + y + j) * ED + by + x] = t[x][y + j];
}

// ---------------- K1: P = x @ W^T + b  (16m x 4n per thread, m-pair accs) ----------------
#define W1BYTES (BK1 * ED * 4)

__global__ __launch_bounds__(256, 2)
void k1_kernel(const float* __restrict__ x, const float* __restrict__ bias) {
    extern __shared__ __align__(16) float sm1[];
    float* xT = sm1;                       // [2][BK1][XTP]  x transposed (non-dup), k-major
    float* wS = sm1 + 2 * BK1 * XTP;       // [2][BK1][ED]   W tile, k-major
    __shared__ __align__(8) u64 mbars[2];
    __shared__ float sq_sm[64][2];

    const int tid = threadIdx.x;
    const int w = tid >> 5, lane = tid & 31;
    const int t0 = blockIdx.x * 64;
    const int mb = (w & 3) * 16;           // 16 rows per warp
    const int nc = (w >> 2) * 128 + lane * 4;  // 4 cols per lane, 128-col half per warp group

    const int xr = tid >> 2, xk = (tid & 3) * 8;
    const float* xp = x + (size_t)(t0 + xr) * IN_DIM + xk;

    u32 wS_u32 = (u32)__cvta_generic_to_shared(wS);
    u32 mb0 = (u32)__cvta_generic_to_shared(&mbars[0]);
    u32 mb1 = mb0 + 8;
    int ph0 = 0, ph1 = 0;

    u64 acc[8][4];
    #pragma unroll
    for (int m = 0; m < 8; ++m)
        #pragma unroll
        for (int p = 0; p < 4; ++p) acc[m][p] = 0ull;

    if (tid == 0) { mbar_init(mb0, 1); mbar_init(mb1, 1); }
    __syncthreads();

    if (tid == 0) { mbar_expect_tx(mb0, W1BYTES); bulk_g2s(wS_u32, g_WT, W1BYTES, mb0); }
    float4 xs0 = *(const float4*)xp;
    float4 xs1 = *(const float4*)(xp + 4);
    {
        float v[8] = {xs0.x, xs0.y, xs0.z, xs0.w, xs1.x, xs1.y, xs1.z, xs1.w};
        #pragma unroll
        for (int i = 0; i < 8; ++i)
            xT[(xk + i) * XTP + xr] = v[i];
    }
    mbar_wait(mb0, ph0); ph0 ^= 1;
    __syncthreads();

    const int NT = IN_DIM / BK1;
    for (int kt = 0; kt < NT; ++kt) {
        const int buf = kt & 1;
        const float* xb = xT + buf * (BK1 * XTP);
        const float* wb = wS + buf * (BK1 * ED);
        if (kt + 1 < NT) {
            if (tid == 0) {
                u32 m = buf ? mb0 : mb1;
                mbar_expect_tx(m, W1BYTES);
                bulk_g2s(wS_u32 + (u32)((buf ^ 1) * W1BYTES),
                         g_WT + (size_t)(kt + 1) * BK1 * ED, W1BYTES, m);
            }
            xs0 = *(const float4*)(xp + (kt + 1) * BK1);
            xs1 = *(const float4*)(xp + (kt + 1) * BK1 + 4);
        }
        #pragma unroll
        for (int k = 0; k < BK1; ++k) {
            const ulonglong2* ap = (const ulonglong2*)(xb + k * XTP + mb);
            ulonglong2 qa0 = ap[0], qa1 = ap[1], qa2 = ap[2], qa3 = ap[3];
            float4 b = *(const float4*)(wb + k * ED + nc);
            u64 B0 = pack2(b.x, b.x), B1 = pack2(b.y, b.y);
            u64 B2 = pack2(b.z, b.z), B3 = pack2(b.w, b.w);
            ffma2(acc[0][0], qa0.x, B0); ffma2(acc[0][1], qa0.x, B1);
            ffma2(acc[0][2], qa0.x, B2); ffma2(acc[0][3], qa0.x, B3);
            ffma2(acc[1][0], qa0.y, B0); ffma2(acc[1][1], qa0.y, B1);
            ffma2(acc[1][2], qa0.y, B2); ffma2(acc[1][3], qa0.y, B3);
            ffma2(acc[2][0], qa1.x, B0); ffma2(acc[2][1], qa1.x, B1);
            ffma2(acc[2][2], qa1.x, B2); ffma2(acc[2][3], qa1.x, B3);
            ffma2(acc[3][0], qa1.y, B0); ffma2(acc[3][1], qa1.y, B1);
            ffma2(acc[3][2], qa1.y, B2); ffma2(acc[3][3], qa1.y, B3);
            ffma2(acc[4][0], qa2.x, B0); ffma2(acc[4][1], qa2.x, B1);
            ffma2(acc[4][2], qa2.x, B2); ffma2(acc[4][3], qa2.x, B3);
            ffma2(acc[5][0], qa2.y, B0); ffma2(acc[5][1], qa2.y, B1);
            ffma2(acc[5][2], qa2.y, B2); ffma2(acc[5][3], qa2.y, B3);
            ffma2(acc[6][0], qa3.x, B0); ffma2(acc[6][1], qa3.x, B1);
            ffma2(acc[6][2], qa3.x, B2); ffma2(acc[6][3], qa3.x, B3);
            ffma2(acc[7][0], qa3.y, B0); ffma2(acc[7][1], qa3.y, B1);
            ffma2(acc[7][2], qa3.y, B2); ffma2(acc[7][3], qa3.y, B3);
        }
        if (kt + 1 < NT) {
            float* xn = xT + (buf ^ 1) * (BK1 * XTP);
            float v[8] = {xs0.x, xs0.y, xs0.z, xs0.w, xs1.x, xs1.y, xs1.z, xs1.w};
            #pragma unroll
            for (int i = 0; i < 8; ++i)
                xn[(xk + i) * XTP + xr] = v[i];
            if (buf) { mbar_wait(mb0, ph0); ph0 ^= 1; }
            else     { mbar_wait(mb1, ph1); ph1 ^= 1; }
        }
        __syncthreads();
    }

    // epilogue: +bias (dup-packed), per-pair sumsq butterfly, store P + g_sq
    float4 b4 = *(const float4*)(bias + nc);
    u64 bp[4];
    bp[0] = pack2(b4.x, b4.x); bp[1] = pack2(b4.y, b4.y);
    bp[2] = pack2(b4.z, b4.z); bp[3] = pack2(b4.w, b4.w);

    u64 sp[8];
    #pragma unroll
    for (int m = 0; m < 8; ++m) {
        sp[m] = 0ull;
        #pragma unroll
        for (int j = 0; j < 4; ++j) {
            fadd2(acc[m][j], bp[j]);
            ffma2(sp[m], acc[m][j], acc[m][j]);
        }
    }
    #pragma unroll
    for (int m = 0; m < 8; ++m)
        #pragma unroll
        for (int o = 16; o; o >>= 1) {
            u64 t = __shfl_xor_sync(0xffffffffu, sp[m], o);
            fadd2(sp[m], t);
        }

    #pragma unroll
    for (int m = 0; m < 8; ++m) {
        float lo[4], hi[4];
        #pragma unroll
        for (int j = 0; j < 4; ++j) unpack2(acc[m][j], lo[j], hi[j]);
        int r = t0 + mb + 2 * m;
        *(float4*)(g_P + (size_t)r * ED + nc)        = make_float4(lo[0], lo[1], lo[2], lo[3]);
        *(float4*)(g_P + (size_t)(r + 1) * ED + nc)  = make_float4(hi[0], hi[1], hi[2], hi[3]);
    }
    if (lane == 0) {
        #pragma unroll
        for (int m = 0; m < 8; ++m) {
            float se, so; unpack2(sp[m], se, so);
            sq_sm[mb + 2 * m][w >> 2]     = se;
            sq_sm[mb + 2 * m + 1][w >> 2] = so;
        }
    }
    __syncthreads();
    if (tid < 64) g_sq[t0 + tid] = sq_sm[tid][0] + sq_sm[tid][1];
}

// ---------------- K2: sims + top-2 + softmax (round-4 form) ----------------
#define C2BYTES (BK2 * NE * 4)

__global__ __launch_bounds__(256, 2)
void k2_kernel(float* __restrict__ out, int ntok) {
    extern __shared__ __align__(16) float sm2[];
    float* PsT = sm2;                      // [ED][PSTP] : P transposed [k][m]
    float* ct  = sm2 + ED * PSTP;          // [2][BK2][NE] center tiles
    __shared__ __align__(8) u64 mbars[2];

    const int tid = threadIdx.x;
    const int w = tid >> 5, lane = tid & 31;
    const int t0 = blockIdx.x * TT;
    const int mb = (w >> 1) * 8;
    const int nh = (w & 1) * 256;
    const int nA = nh + lane * 4, nB = nh + 128 + lane * 4;

    u32 ct_u32 = (u32)__cvta_generic_to_shared(ct);
    u32 mb0 = (u32)__cvta_generic_to_shared(&mbars[0]);
    u32 mb1 = mb0 + 8;
    int ph0 = 0, ph1 = 0;

    if (tid == 0) { mbar_init(mb0, 1); mbar_init(mb1, 1); }
    __syncthreads();
    if (tid == 0) { mbar_expect_tx(mb0, C2BYTES); bulk_g2s(ct_u32, g_cnT, C2BYTES, mb0); }

    // transpose P tile into PsT (overlaps with bulk copy)
    const int pr = tid >> 3, pcq = (tid & 7) * 4;
    #pragma unroll
    for (int j = 0; j < 8; ++j) {
        int c = pcq + 32 * j;
        float4 v = *(const float4*)(g_P + (size_t)(t0 + pr) * ED + c);
        PsT[(c + 0) * PSTP + pr] = v.x;
        PsT[(c + 1) * PSTP + pr] = v.y;
        PsT[(c + 2) * PSTP + pr] = v.z;
        PsT[(c + 3) * PSTP + pr] = v.w;
    }
    mbar_wait(mb0, ph0); ph0 ^= 1;
    __syncthreads();

    u64 acc[4][8];
    #pragma unroll
    for (int p = 0; p < 4; ++p)
        #pragma unroll
        for (int j = 0; j < 8; ++j) acc[p][j] = 0ull;

    const int NT = ED / BK2;
    for (int kt = 0; kt < NT; ++kt) {
        const int buf = kt & 1;
        const float* cb = ct + buf * (BK2 * NE);
        if (kt + 1 < NT && tid == 0) {
            u32 m = buf ? mb0 : mb1;
            mbar_expect_tx(m, C2BYTES);
            bulk_g2s(ct_u32 + (u32)((buf ^ 1) * C2BYTES),
                     g_cnT + (size_t)(kt + 1) * BK2 * NE, C2BYTES, m);
        }
        #pragma unroll
        for (int k = 0; k < BK2; ++k) {
            const int kk = kt * BK2 + k;
            const u64* ap = (const u64*)(PsT + kk * PSTP + mb);
            u64 a0 = ap[0], a1 = ap[1], a2 = ap[2], a3 = ap[3];
            float4 b0 = *(const float4*)(cb + k * NE + nA);
            float4 b1 = *(const float4*)(cb + k * NE + nB);
            u64 bb0 = pack2(b0.x, b0.x), bb1 = pack2(b0.y, b0.y);
            u64 bb2 = pack2(b0.z, b0.z), bb3 = pack2(b0.w, b0.w);
            u64 bb4 = pack2(b1.x, b1.x), bb5 = pack2(b1.y, b1.y);
            u64 bb6 = pack2(b1.z, b1.z), bb7 = pack2(b1.w, b1.w);
            ffma2(acc[0][0], a0, bb0); ffma2(acc[0][1], a0, bb1);
            ffma2(acc[0][2], a0, bb2); ffma2(acc[0][3], a0, bb3);
            ffma2(acc[0][4], a0, bb4); ffma2(acc[0][5], a0, bb5);
            ffma2(acc[0][6], a0, bb6); ffma2(acc[0][7], a0, bb7);
            ffma2(acc[1][0], a1, bb0); ffma2(acc[1][1], a1, bb1);
            ffma2(acc[1][2], a1, bb2); ffma2(acc[1][3], a1, bb3);
            ffma2(acc[1][4], a1, bb4); ffma2(acc[1][5], a1, bb5);
            ffma2(acc[1][6], a1, bb6); ffma2(acc[1][7], a1, bb7);
            ffma2(acc[2][0], a2, bb0); ffma2(acc[2][1], a2, bb1);
            ffma2(acc[2][2], a2, bb2); ffma2(acc[2][3], a2, bb3);
            ffma2(acc[2][4], a2, bb4); ffma2(acc[2][5], a2, bb5);
            ffma2(acc[2][6], a2, bb6); ffma2(acc[2][7], a2, bb7);
            ffma2(acc[3][0], a3, bb0); ffma2(acc[3][1], a3, bb1);
            ffma2(acc[3][2], a3, bb2); ffma2(acc[3][3], a3, bb3);
            ffma2(acc[3][4], a3, bb4); ffma2(acc[3][5], a3, bb5);
            ffma2(acc[3][6], a3, bb6); ffma2(acc[3][7], a3, bb7);
        }
        if (kt + 1 < NT) {
            if (buf) { mbar_wait(mb0, ph0); ph0 ^= 1; }
            else     { mbar_wait(mb1, ph1); ph1 ^= 1; }
        }
        __syncthreads();
    }

    // per-thread -> per-warp top-2 over this warp's 256-expert half
    float v1[8], v2[8]; int i1[8], i2[8];
    #pragma unroll
    for (int r = 0; r < 8; ++r) { v1[r] = -INFINITY; v2[r] = -INFINITY; i1[r] = 0; i2[r] = 0; }
    #pragma unroll
    for (int p = 0; p < 4; ++p)
        #pragma unroll
        for (int j = 0; j < 8; ++j) {
            float lo, hi; unpack2(acc[p][j], lo, hi);
            int gi = (j < 4) ? (nA + j) : (nB + j - 4);
            upd(lo, gi, v1[2 * p],     i1[2 * p],     v2[2 * p],     i2[2 * p]);
            upd(hi, gi, v1[2 * p + 1], i1[2 * p + 1], v2[2 * p + 1], i2[2 * p + 1]);
        }
    #pragma unroll
    for (int r = 0; r < 8; ++r)
        #pragma unroll
        for (int o = 16; o; o >>= 1) {
            float o1 = __shfl_xor_sync(0xffffffffu, v1[r], o);
            int  oi1 = __shfl_xor_sync(0xffffffffu, i1[r], o);
            float o2 = __shfl_xor_sync(0xffffffffu, v2[r], o);
            int  oi2 = __shfl_xor_sync(0xffffffffu, i2[r], o);
            upd(o1, oi1, v1[r], i1[r], v2[r], i2[r]);
            upd(o2, oi2, v1[r], i1[r], v2[r], i2[r]);
        }

    // cross-half merge via smem (reuse ct region, safe after last sync)
    float4* mg = (float4*)ct;              // [TT][2]
    if (lane == 0) {
        #pragma unroll
        for (int r = 0; r < 8; ++r)
            mg[(mb + r) * 2 + (w & 1)] =
                make_float4(v1[r], __int_as_float(i1[r]), v2[r], __int_as_float(i2[r]));
    }
    __syncthreads();

    if (tid < TT) {
        float4 A = mg[tid * 2 + 0];
        float4 B = mg[tid * 2 + 1];
        float V1 = A.x, V2 = A.z;
        int I1 = __float_as_int(A.y), I2 = __float_as_int(A.w);
        upd(B.x, __float_as_int(B.y), V1, I1, V2, I2);
        upd(B.z, __float_as_int(B.w), V1, I1, V2, I2);
        int token = t0 + tid;
        float inv = 1.f / fmaxf(sqrtf(g_sq[token]), 1e-12f);
        float e2 = expf((V2 - V1) * inv);
        float den = 1.f + e2;
        out[2 * token]     = 1.f / den;
        out[2 * token + 1] = e2 / den;
        float* oi = out + 2 * (size_t)ntok;
        oi[2 * token]     = (float)I1;
        oi[2 * token + 1] = (float)I2;
    }
}

extern "C" void kernel_launch(void* const* d_in, const int* in_sizes, int n_in,
                              void* d_out, int out_size) {
    const float* x = (const float*)d_in[0];
    const float* W = (const float*)d_in[1];
    const float* b = (const float*)d_in[2];
    const float* c = (const float*)d_in[3];
    int ntok = in_sizes[0] / IN_DIM;   // 131072

    cnorm_kernel<<<NE, ED>>>(c);
    prep_wt_kernel<<<dim3(IN_DIM / 32, ED / 32), dim3(32, 8)>>>(W);

    int smem1 = (2 * BK1 * XTP + 2 * BK1 * ED) * (int)sizeof(float);   // 82944 B
    cudaFuncSetAttribute(k1_kernel, cudaFuncAttributeMaxDynamicSharedMemorySize, smem1);
    k1_kernel<<<ntok / 64, 256, smem1>>>(x, b);

    int smem2 = (ED * PSTP + 2 * BK2 * NE) * (int)sizeof(float);       // 100352 B
    cudaFuncSetAttribute(k2_kernel, cudaFuncAttributeMaxDynamicSharedMemorySize, smem2);
    k2_kernel<<<ntok / TT, 256, smem2>>>((float*)d_out, ntok);
}

// round 11
// speedup vs baseline: 1.5173x; 1.0242x over previous
#include <cuda_runtime.h>
#include <math.h>
#include <stdint.h>

#define IN_DIM 1024
#define ED 256
#define NE 512
#define NTOK_MAX 131072
#define TT 32
#define XTP 68
#define PSTP 36
#define BK1 32
#define BK2 16

typedef unsigned long long u64;
typedef uint32_t u32;

__device__ __align__(16) float g_WT[IN_DIM * ED];     // W transposed [k][n]
__device__ __align__(16) float g_cnT[ED * NE];        // normalized centers [k][e]
__device__ __align__(16) float g_P[(size_t)NTOK_MAX * ED];
__device__ float g_sq[NTOK_MAX];

static __device__ __forceinline__ u64 pack2(float lo, float hi) {
    u64 r; asm("mov.b64 %0, {%1, %2};" : "=l"(r) : "f"(lo), "f"(hi)); return r;
}
static __device__ __forceinline__ void unpack2(u64 v, float& lo, float& hi) {
    asm("mov.b64 {%0, %1}, %2;" : "=f"(lo), "=f"(hi) : "l"(v));
}
static __device__ __forceinline__ void ffma2(u64& d, u64 a, u64 b) {
    asm("fma.rn.f32x2 %0, %1, %2, %0;" : "+l"(d) : "l"(a), "l"(b));
}
static __device__ __forceinline__ void fadd2(u64& d, u64 a) {
    asm("add.rn.f32x2 %0, %0, %1;" : "+l"(d) : "l"(a));
}

// ---- bulk async copy + mbarrier helpers ----
static __device__ __forceinline__ void mbar_init(u32 mbar, u32 cnt) {
    asm volatile("mbarrier.init.shared.b64 [%0], %1;" :: "r"(mbar), "r"(cnt) : "memory");
}
static __device__ __forceinline__ void mbar_expect_tx(u32 mbar, u32 bytes) {
    asm volatile("mbarrier.arrive.expect_tx.shared.b64 _, [%0], %1;" :: "r"(mbar), "r"(bytes) : "memory");
}
static __device__ __forceinline__ void bulk_g2s(u32 dst, const float* src,
                                                u32 bytes, u32 mbar) {
    asm volatile("cp.async.bulk.shared::cta.global.mbarrier::complete_tx::bytes [%0], [%1], %2, [%3];"
                 :: "r"(dst), "l"(src), "r"(bytes), "r"(mbar) : "memory");
}
static __device__ __forceinline__ void mbar_wait(u32 mbar, u32 parity) {
    u32 done;
    asm volatile(
        "{\n\t.reg .pred p;\n\t"
        "mbarrier.try_wait.parity.acquire.cta.shared::cta.b64 p, [%1], %2;\n\t"
        "selp.b32 %0, 1, 0, p;\n\t}"
        : "=r"(done) : "r"(mbar), "r"(parity) : "memory");
    if (!done) {
        asm volatile(
            "{\n\t.reg .pred P1;\n\t"
            "WL_%=:\n\t"
            "mbarrier.try_wait.parity.acquire.cta.shared::cta.b64 P1, [%0], %1, 0x989680;\n\t"
            "@P1 bra.uni WD_%=;\n\t"
            "bra.uni WL_%=;\n\t"
            "WD_%=:\n\t}"
            :: "r"(mbar), "r"(parity) : "memory");
    }
}

static __device__ __forceinline__ void upd(float v, int i,
                                           float& v1, int& i1, float& v2, int& i2) {
    if (v > v1 || (v == v1 && i < i1)) { v2 = v1; i2 = i1; v1 = v; i1 = i; }
    else if (v > v2 || (v == v2 && i < i2)) { v2 = v; i2 = i; }
}

// ---------------- prep: normalize centers -> g_cnT [k][e] ----------------
__global__ void cnorm_kernel(const float* __restrict__ centers) {
    __shared__ float ws[8];
    int e = blockIdx.x, t = threadIdx.x;
    float v = centers[e * ED + t];
    float s = v * v;
    #pragma unroll
    for (int o = 16; o; o >>= 1) s += __shfl_xor_sync(0xffffffffu, s, o);
    if ((t & 31) == 0) ws[t >> 5] = s;
    __syncthreads();
    float tot = 0.f;
    #pragma unroll
    for (int i = 0; i < 8; ++i) tot += ws[i];
    float norm = fmaxf(sqrtf(tot), 1e-12f);
    g_cnT[t * NE + e] = v / norm;
}

// ---------------- prep: transpose W [n][k] -> g_WT [k][n] ----------------
__global__ void prep_wt_kernel(const float* __restrict__ W) {
    __shared__ float t[32][33];
    int bx = blockIdx.x * 32;
    int by = blockIdx.y * 32;
    int x = threadIdx.x, y = threadIdx.y;
    #pragma unroll
    for (int j = 0; j < 32; j += 8)
        t[y + j][x] = W[(size_t)(by + y + j) * IN_DIM + bx + x];
    __syncthreads();
    #pragma unroll
    for (int j = 0; j < 32; j += 8)
        g_WT[(size_t)(bx + y + j) * ED + by + x] = t[x][y + j];
}

// ---------------- K1: P = x @ W^T + b  (16m x 4n per thread, m-pair accs) ----------------
#define W1BYTES (BK1 * ED * 4)

__global__ __launch_bounds__(256, 2)
void k1_kernel(const float* __restrict__ x, const float* __restrict__ bias) {
    extern __shared__ __align__(16) float sm1[];
    float* xT = sm1;                       // [2][BK1][XTP]  x transposed (non-dup), k-major
    float* wS = sm1 + 2 * BK1 * XTP;       // [2][BK1][ED]   W tile, k-major
    __shared__ __align__(8) u64 mbars[2];
    __shared__ float sq_sm[64][2];

    const int tid = threadIdx.x;
    const int w = tid >> 5, lane = tid & 31;
    const int t0 = blockIdx.x * 64;
    const int mb = (w & 3) * 16;           // 16 rows per warp
    const int nc = (w >> 2) * 128 + lane * 4;  // 4 cols per lane, 128-col half per warp group

    const int xr = tid >> 2, xk = (tid & 3) * 8;
    const float* xp = x + (size_t)(t0 + xr) * IN_DIM + xk;

    u32 wS_u32 = (u32)__cvta_generic_to_shared(wS);
    u32 mb0 = (u32)__cvta_generic_to_shared(&mbars[0]);
    u32 mb1 = mb0 + 8;
    int ph0 = 0, ph1 = 0;

    u64 acc[8][4];
    #pragma unroll
    for (int m = 0; m < 8; ++m)
        #pragma unroll
        for (int p = 0; p < 4; ++p) acc[m][p] = 0ull;

    if (tid == 0) { mbar_init(mb0, 1); mbar_init(mb1, 1); }
    __syncthreads();

    if (tid == 0) { mbar_expect_tx(mb0, W1BYTES); bulk_g2s(wS_u32, g_WT, W1BYTES, mb0); }
    float4 xs0 = *(const float4*)xp;
    float4 xs1 = *(const float4*)(xp + 4);
    {
        float v[8] = {xs0.x, xs0.y, xs0.z, xs0.w, xs1.x, xs1.y, xs1.z, xs1.w};
        #pragma unroll
        for (int i = 0; i < 8; ++i)
            xT[(xk + i) * XTP + xr] = v[i];
    }
    mbar_wait(mb0, ph0); ph0 ^= 1;
    __syncthreads();

    const int NT = IN_DIM / BK1;
    for (int kt = 0; kt < NT; ++kt) {
        const int buf = kt & 1;
        const float* xb = xT + buf * (BK1 * XTP);
        const float* wb = wS + buf * (BK1 * ED);
        if (kt + 1 < NT) {
            if (tid == 0) {
                u32 m = buf ? mb0 : mb1;
                mbar_expect_tx(m, W1BYTES);
                bulk_g2s(wS_u32 + (u32)((buf ^ 1) * W1BYTES),
                         g_WT + (size_t)(kt + 1) * BK1 * ED, W1BYTES, m);
            }
            xs0 = *(const float4*)(xp + (kt + 1) * BK1);
            xs1 = *(const float4*)(xp + (kt + 1) * BK1 + 4);
        }
        #pragma unroll
        for (int k = 0; k < BK1; ++k) {
            const ulonglong2* ap = (const ulonglong2*)(xb + k * XTP + mb);
            ulonglong2 qa0 = ap[0], qa1 = ap[1], qa2 = ap[2], qa3 = ap[3];
            float4 b = *(const float4*)(wb + k * ED + nc);
            u64 B0 = pack2(b.x, b.x), B1 = pack2(b.y, b.y);
            u64 B2 = pack2(b.z, b.z), B3 = pack2(b.w, b.w);
            ffma2(acc[0][0], qa0.x, B0); ffma2(acc[0][1], qa0.x, B1);
            ffma2(acc[0][2], qa0.x, B2); ffma2(acc[0][3], qa0.x, B3);
            ffma2(acc[1][0], qa0.y, B0); ffma2(acc[1][1], qa0.y, B1);
            ffma2(acc[1][2], qa0.y, B2); ffma2(acc[1][3], qa0.y, B3);
            ffma2(acc[2][0], qa1.x, B0); ffma2(acc[2][1], qa1.x, B1);
            ffma2(acc[2][2], qa1.x, B2); ffma2(acc[2][3], qa1.x, B3);
            ffma2(acc[3][0], qa1.y, B0); ffma2(acc[3][1], qa1.y, B1);
            ffma2(acc[3][2], qa1.y, B2); ffma2(acc[3][3], qa1.y, B3);
            ffma2(acc[4][0], qa2.x, B0); ffma2(acc[4][1], qa2.x, B1);
            ffma2(acc[4][2], qa2.x, B2); ffma2(acc[4][3], qa2.x, B3);
            ffma2(acc[5][0], qa2.y, B0); ffma2(acc[5][1], qa2.y, B1);
            ffma2(acc[5][2], qa2.y, B2); ffma2(acc[5][3], qa2.y, B3);
            ffma2(acc[6][0], qa3.x, B0); ffma2(acc[6][1], qa3.x, B1);
            ffma2(acc[6][2], qa3.x, B2); ffma2(acc[6][3], qa3.x, B3);
            ffma2(acc[7][0], qa3.y, B0); ffma2(acc[7][1], qa3.y, B1);
            ffma2(acc[7][2], qa3.y, B2); ffma2(acc[7][3], qa3.y, B3);
        }
        if (kt + 1 < NT) {
            float* xn = xT + (buf ^ 1) * (BK1 * XTP);
            float v[8] = {xs0.x, xs0.y, xs0.z, xs0.w, xs1.x, xs1.y, xs1.z, xs1.w};
            #pragma unroll
            for (int i = 0; i < 8; ++i)
                xn[(xk + i) * XTP + xr] = v[i];
            if (buf) { mbar_wait(mb0, ph0); ph0 ^= 1; }
            else     { mbar_wait(mb1, ph1); ph1 ^= 1; }
        }
        __syncthreads();
    }

    // epilogue: +bias (dup-packed), per-pair sumsq butterfly, store P + g_sq
    float4 b4 = *(const float4*)(bias + nc);
    u64 bp[4];
    bp[0] = pack2(b4.x, b4.x); bp[1] = pack2(b4.y, b4.y);
    bp[2] = pack2(b4.z, b4.z); bp[3] = pack2(b4.w, b4.w);

    u64 sp[8];
    #pragma unroll
    for (int m = 0; m < 8; ++m) {
        sp[m] = 0ull;
        #pragma unroll
        for (int j = 0; j < 4; ++j) {
            fadd2(acc[m][j], bp[j]);
            ffma2(sp[m], acc[m][j], acc[m][j]);
        }
    }
    #pragma unroll
    for (int m = 0; m < 8; ++m)
        #pragma unroll
        for (int o = 16; o; o >>= 1) {
            u64 t = __shfl_xor_sync(0xffffffffu, sp[m], o);
            fadd2(sp[m], t);
        }

    #pragma unroll
    for (int m = 0; m < 8; ++m) {
        float lo[4], hi[4];
        #pragma unroll
        for (int j = 0; j < 4; ++j) unpack2(acc[m][j], lo[j], hi[j]);
        int r = t0 + mb + 2 * m;
        *(float4*)(g_P + (size_t)r * ED + nc)        = make_float4(lo[0], lo[1], lo[2], lo[3]);
        *(float4*)(g_P + (size_t)(r + 1) * ED + nc)  = make_float4(hi[0], hi[1], hi[2], hi[3]);
    }
    if (lane == 0) {
        #pragma unroll
        for (int m = 0; m < 8; ++m) {
            float se, so; unpack2(sp[m], se, so);
            sq_sm[mb + 2 * m][w >> 2]     = se;
            sq_sm[mb + 2 * m + 1][w >> 2] = so;
        }
    }
    __syncthreads();
    if (tid < 64) g_sq[t0 + tid] = sq_sm[tid][0] + sq_sm[tid][1];
}

// ---------------- K2: sims + top-2 + softmax (16 tokens x 128 experts/warp, smem merge) ----------------
#define C2BYTES (BK2 * NE * 4)
#define MGP 129     // mg pitch in float4 units

__global__ __launch_bounds__(256, 2)
void k2_kernel(float* __restrict__ out, int ntok) {
    extern __shared__ __align__(16) float sm2[];
    float* PsT = sm2;                      // [ED][PSTP] : P transposed [k][m]
    float* ct  = sm2 + ED * PSTP;          // [2][BK2][NE] center tiles
    __shared__ __align__(8) u64 mbars[2];

    const int tid = threadIdx.x;
    const int w = tid >> 5, lane = tid & 31;
    const int t0 = blockIdx.x * TT;
    const int g = w >> 2, h = w & 3;
    const int mb = g * 16;                 // 16 tokens per warp
    const int nc = h * 128 + lane * 4;     // 4 experts per lane within 128-expert group

    u32 ct_u32 = (u32)__cvta_generic_to_shared(ct);
    u32 mb0 = (u32)__cvta_generic_to_shared(&mbars[0]);
    u32 mb1 = mb0 + 8;
    int ph0 = 0, ph1 = 0;

    if (tid == 0) { mbar_init(mb0, 1); mbar_init(mb1, 1); }
    __syncthreads();
    if (tid == 0) { mbar_expect_tx(mb0, C2BYTES); bulk_g2s(ct_u32, g_cnT, C2BYTES, mb0); }

    // transpose P tile into PsT (overlaps with bulk copy)
    const int pr = tid >> 3, pcq = (tid & 7) * 4;
    #pragma unroll
    for (int j = 0; j < 8; ++j) {
        int c = pcq + 32 * j;
        float4 v = *(const float4*)(g_P + (size_t)(t0 + pr) * ED + c);
        PsT[(c + 0) * PSTP + pr] = v.x;
        PsT[(c + 1) * PSTP + pr] = v.y;
        PsT[(c + 2) * PSTP + pr] = v.z;
        PsT[(c + 3) * PSTP + pr] = v.w;
    }
    mbar_wait(mb0, ph0); ph0 ^= 1;
    __syncthreads();

    u64 acc[8][4];
    #pragma unroll
    for (int m = 0; m < 8; ++m)
        #pragma unroll
        for (int p = 0; p < 4; ++p) acc[m][p] = 0ull;

    const int NT = ED / BK2;
    for (int kt = 0; kt < NT; ++kt) {
        const int buf = kt & 1;
        const float* cb = ct + buf * (BK2 * NE);
        if (kt + 1 < NT && tid == 0) {
            u32 m = buf ? mb0 : mb1;
            mbar_expect_tx(m, C2BYTES);
            bulk_g2s(ct_u32 + (u32)((buf ^ 1) * C2BYTES),
                     g_cnT + (size_t)(kt + 1) * BK2 * NE, C2BYTES, m);
        }
        #pragma unroll
        for (int k = 0; k < BK2; ++k) {
            const int kk = kt * BK2 + k;
            const ulonglong2* ap = (const ulonglong2*)(PsT + kk * PSTP + mb);
            ulonglong2 qa0 = ap[0], qa1 = ap[1], qa2 = ap[2], qa3 = ap[3];
            float4 b = *(const float4*)(cb + k * NE + nc);
            u64 B0 = pack2(b.x, b.x), B1 = pack2(b.y, b.y);
            u64 B2 = pack2(b.z, b.z), B3 = pack2(b.w, b.w);
            ffma2(acc[0][0], qa0.x, B0); ffma2(acc[0][1], qa0.x, B1);
            ffma2(acc[0][2], qa0.x, B2); ffma2(acc[0][3], qa0.x, B3);
            ffma2(acc[1][0], qa0.y, B0); ffma2(acc[1][1], qa0.y, B1);
            ffma2(acc[1][2], qa0.y, B2); ffma2(acc[1][3], qa0.y, B3);
            ffma2(acc[2][0], qa1.x, B0); ffma2(acc[2][1], qa1.x, B1);
            ffma2(acc[2][2], qa1.x, B2); ffma2(acc[2][3], qa1.x, B3);
            ffma2(acc[3][0], qa1.y, B0); ffma2(acc[3][1], qa1.y, B1);
            ffma2(acc[3][2], qa1.y, B2); ffma2(acc[3][3], qa1.y, B3);
            ffma2(acc[4][0], qa2.x, B0); ffma2(acc[4][1], qa2.x, B1);
            ffma2(acc[4][2], qa2.x, B2); ffma2(acc[4][3], qa2.x, B3);
            ffma2(acc[5][0], qa2.y, B0); ffma2(acc[5][1], qa2.y, B1);
            ffma2(acc[5][2], qa2.y, B2); ffma2(acc[5][3], qa2.y, B3);
            ffma2(acc[6][0], qa3.x, B0); ffma2(acc[6][1], qa3.x, B1);
            ffma2(acc[6][2], qa3.x, B2); ffma2(acc[6][3], qa3.x, B3);
            ffma2(acc[7][0], qa3.y, B0); ffma2(acc[7][1], qa3.y, B1);
            ffma2(acc[7][2], qa3.y, B2); ffma2(acc[7][3], qa3.y, B3);
        }
        if (kt + 1 < NT) {
            if (buf) { mbar_wait(mb0, ph0); ph0 ^= 1; }
            else     { mbar_wait(mb1, ph1); ph1 ^= 1; }
        }
        __syncthreads();
    }

    // per-thread top-2 over this thread's 4 experts, per token slot
    float v1[16], v2[16]; int i1[16], i2[16];
    #pragma unroll
    for (int s = 0; s < 16; ++s) { v1[s] = -INFINITY; v2[s] = -INFINITY; i1[s] = 0; i2[s] = 0; }
    #pragma unroll
    for (int m = 0; m < 8; ++m)
        #pragma unroll
        for (int j = 0; j < 4; ++j) {
            float lo, hi; unpack2(acc[m][j], lo, hi);
            int gi = nc + j;
            upd(lo, gi, v1[2 * m],     i1[2 * m],     v2[2 * m],     i2[2 * m]);
            upd(hi, gi, v1[2 * m + 1], i1[2 * m + 1], v2[2 * m + 1], i2[2 * m + 1]);
        }

    // write per-lane top2 to mg (overlaid on ALL of sm2; PsT+ct dead after final sync above)
    float4* mg = (float4*)sm2;             // [TT][MGP] ; entry = h*32 + lane
    #pragma unroll
    for (int s = 0; s < 16; ++s)
        mg[(mb + s) * MGP + h * 32 + lane] =
            make_float4(v1[s], __int_as_float(i1[s]), v2[s], __int_as_float(i2[s]));
    __syncthreads();

    // merge: 128 threads, (token, quarter); scan 32 entries, then shfl merge over 4 quarters
    if (tid < 128) {
        const int token = tid >> 2, q = tid & 3;
        const float4* row = mg + token * MGP + q * 32;
        float4 E = row[0];
        float V1 = E.x, V2 = E.z;
        int I1 = __float_as_int(E.y), I2 = __float_as_int(E.w);
        #pragma unroll 8
        for (int e = 1; e < 32; ++e) {
            E = row[e];
            upd(E.x, __float_as_int(E.y), V1, I1, V2, I2);
            upd(E.z, __float_as_int(E.w), V1, I1, V2, I2);
        }
        #pragma unroll
        for (int off = 1; off <= 2; off <<= 1) {
            float o1 = __shfl_xor_sync(0xffffffffu, V1, off);
            int  oi1 = __shfl_xor_sync(0xffffffffu, I1, off);
            float o2 = __shfl_xor_sync(0xffffffffu, V2, off);
            int  oi2 = __shfl_xor_sync(0xffffffffu, I2, off);
            upd(o1, oi1, V1, I1, V2, I2);
            upd(o2, oi2, V1, I1, V2, I2);
        }
        if (q == 0) {
            int tok = t0 + token;
            float inv = 1.f / fmaxf(sqrtf(g_sq[tok]), 1e-12f);
            float e2 = expf((V2 - V1) * inv);
            float den = 1.f + e2;
            out[2 * tok]     = 1.f / den;
            out[2 * tok + 1] = e2 / den;
            float* oi = out + 2 * (size_t)ntok;
            oi[2 * tok]     = (float)I1;
            oi[2 * tok + 1] = (float)I2;
        }
    }
}

extern "C" void kernel_launch(void* const* d_in, const int* in_sizes, int n_in,
                              void* d_out, int out_size) {
    const float* x = (const float*)d_in[0];
    const float* W = (const float*)d_in[1];
    const float* b = (const float*)d_in[2];
    const float* c = (const float*)d_in[3];
    int ntok = in_sizes[0] / IN_DIM;   // 131072

    cnorm_kernel<<<NE, ED>>>(c);
    prep_wt_kernel<<<dim3(IN_DIM / 32, ED / 32), dim3(32, 8)>>>(W);

    int smem1 = (2 * BK1 * XTP + 2 * BK1 * ED) * (int)sizeof(float);   // 82944 B
    cudaFuncSetAttribute(k1_kernel, cudaFuncAttributeMaxDynamicSharedMemorySize, smem1);
    k1_kernel<<<ntok / 64, 256, smem1>>>(x, b);

    int smem2 = (ED * PSTP + 2 * BK2 * NE) * (int)sizeof(float);       // 102400 B
    cudaFuncSetAttribute(k2_kernel, cudaFuncAttributeMaxDynamicSharedMemorySize, smem2);
    k2_kernel<<<ntok / TT, 256, smem2>>>((float*)d_out, ntok);
}